// round 2
// baseline (speedup 1.0000x reference)
#include <cuda_runtime.h>
#include <cstddef>

// GroupedESNCell: T=4096 sequential steps; per step 8 matvecs (2048x2048),
// per-group norm, leaky normalized update.
//
// Persistent kernel, 128 CTAs (16 per group), one custom grid barrier per step.
// Each CTA owns 128 output rows of one group, keeps the full group hidden
// state (2048 floats) redundantly in shared memory, so after the single
// barrier it can rebuild h_new locally from the global `pre` buffer.

#define G 8
#define H 2048
#define T_STEPS 4096
#define NCTA 128
#define CTAS_PER_GROUP (NCTA / G)           // 16
#define ROWS_PER_CTA (H / CTAS_PER_GROUP)   // 128
#define THREADS 256
#define NWARPS (THREADS / 32)               // 8
#define ROWS_PER_WARP (ROWS_PER_CTA / NWARPS) // 16
#define RADIUS_F 100.0f
#define LEAKY_F 1.0f
#define K4 (H / (4 * 32))                   // 16 float4 chunks per lane per row

// Global scratch (allocation-free): double-buffered by step parity.
__device__ float g_pre[2][G * H];
__device__ float g_psq[2][NCTA];
__device__ unsigned int g_cnt = 0;
__device__ unsigned int g_epoch = 0;

__global__ __launch_bounds__(THREADS, 1)
void esn_persistent_kernel(const float* __restrict__ x,
                           const float* __restrict__ W_ih,
                           const float* __restrict__ W_hh,
                           float* __restrict__ out)
{
    __shared__ float h_sh[H];            // full group hidden state
    __shared__ float x_sh[T_STEPS];      // whole input sequence (16 KB)
    __shared__ float wih_sh[ROWS_PER_CTA];
    __shared__ float red_sh[NWARPS];
    __shared__ float coef_sh;

    const int tid  = threadIdx.x;
    const int cta  = blockIdx.x;
    const int g    = cta / CTAS_PER_GROUP;
    const int sub  = cta % CTAS_PER_GROUP;
    const int rowbase = sub * ROWS_PER_CTA;
    const int warp = tid >> 5;
    const int lane = tid & 31;

    const float lr   = (LEAKY_F * (float)(G - g)) / (float)G;
    const float leak = 1.0f - lr;

    const float* Wg = W_hh + (size_t)g * H * H;
    const float4* hs4 = (const float4*)h_sh;

    // ---- init shared state ----
    for (int i = tid; i < H; i += THREADS) h_sh[i] = 0.0f;
    for (int i = tid; i < T_STEPS; i += THREADS) x_sh[i] = x[i];
    if (tid < ROWS_PER_CTA) wih_sh[tid] = W_ih[rowbase + tid];
    __syncthreads();

    for (int t = 0; t < T_STEPS; ++t) {
        const int par = t & 1;
        const float xt = x_sh[t];

        // ================= Phase A: matvec for my 128 rows =================
        float warp_sq = 0.0f;
        const int wrow0 = rowbase + warp * ROWS_PER_WARP;

        #pragma unroll 1
        for (int r = 0; r < ROWS_PER_WARP; r += 2) {
            const int i0 = wrow0 + r;
            const float4* w0 = (const float4*)(Wg + (size_t)i0 * H);
            const float4* w1 = (const float4*)(Wg + (size_t)(i0 + 1) * H);
            float a0 = 0.0f, a1 = 0.0f;
            #pragma unroll
            for (int k = 0; k < K4; ++k) {
                const int idx = lane + 32 * k;
                float4 hv = hs4[idx];
                float4 v0 = w0[idx];
                float4 v1 = w1[idx];
                a0 += v0.x * hv.x + v0.y * hv.y + v0.z * hv.z + v0.w * hv.w;
                a1 += v1.x * hv.x + v1.y * hv.y + v1.z * hv.z + v1.w * hv.w;
            }
            #pragma unroll
            for (int s = 16; s > 0; s >>= 1) {
                a0 += __shfl_xor_sync(0xffffffffu, a0, s);
                a1 += __shfl_xor_sync(0xffffffffu, a1, s);
            }
            const float pre0 = a0 + xt * wih_sh[i0 - rowbase];
            const float pre1 = a1 + xt * wih_sh[i0 + 1 - rowbase];
            if (lane == 0) {
                float2 p2 = make_float2(pre0, pre1);
                // L2-only store: other CTAs read this after the barrier
                __stcg((float2*)&g_pre[par][g * H + i0], p2);
                warp_sq += pre0 * pre0 + pre1 * pre1;
            }
        }
        if (lane == 0) red_sh[warp] = warp_sq;
        __syncthreads();
        if (tid == 0) {
            float s = 0.0f;
            #pragma unroll
            for (int w = 0; w < NWARPS; ++w) s += red_sh[w];
            __stcg(&g_psq[par][cta], s);
        }

        // ================= Grid barrier (one per step) =================
        __threadfence();  // cumulative release of this CTA's g_pre/g_psq
        if (tid == 0) {
            volatile unsigned int* ve = (volatile unsigned int*)&g_epoch;
            const unsigned int snap = *ve;        // snapshot before arriving
            const unsigned int old = atomicAdd(&g_cnt, 1u);
            if (old == NCTA - 1u) {
                g_cnt = 0u;                        // safe: next arrivals gated on epoch
                __threadfence();
                atomicAdd(&g_epoch, 1u);
            } else {
                while (*ve == snap) { }
            }
        }
        __syncthreads();
        __threadfence();  // acquire side

        // ================= Phase B: norm + state update (redundant per CTA) ====
        if (tid == 0) {
            float s = 0.0f;
            #pragma unroll
            for (int c = 0; c < CTAS_PER_GROUP; ++c)
                s += __ldcg(&g_psq[par][g * CTAS_PER_GROUP + c]);
            coef_sh = lr * RADIUS_F * rsqrtf(s);
        }
        __syncthreads();
        const float cb = coef_sh;
        const float4* preg = (const float4*)&g_pre[par][g * H];
        float4* hmut = (float4*)h_sh;
        #pragma unroll
        for (int k = 0; k < H / (4 * THREADS); ++k) {   // 2 iterations
            const int idx = tid + THREADS * k;
            float4 p  = __ldcg(&preg[idx]);             // bypass L1 (stale-line safety)
            float4 hv = hmut[idx];
            hv.x = leak * hv.x + cb * p.x;
            hv.y = leak * hv.y + cb * p.y;
            hv.z = leak * hv.z + cb * p.z;
            hv.w = leak * hv.w + cb * p.w;
            hmut[idx] = hv;
        }
        __syncthreads();

        // write my slice of the output row (each element written exactly once)
        if (tid < ROWS_PER_CTA) {
            out[(size_t)t * (G * H) + (size_t)g * H + rowbase + tid] =
                h_sh[rowbase + tid];
        }
        // no extra sync needed: Phase A next step only READS h_sh; the next
        // Phase-B write to h_sh is gated by the next grid barrier + syncthreads.
    }
}

extern "C" void kernel_launch(void* const* d_in, const int* in_sizes, int n_in,
                              void* d_out, int out_size)
{
    const float* x    = (const float*)d_in[0];   // [T, 1]
    const float* W_ih = (const float*)d_in[1];   // [H, 1]
    const float* W_hh = (const float*)d_in[2];   // [G, H, H]
    float* out = (float*)d_out;                  // [T, G*H]

    esn_persistent_kernel<<<NCTA, THREADS>>>(x, W_ih, W_hh, out);
}

// round 3
// speedup vs baseline: 1.0069x; 1.0069x over previous
#include <cuda_runtime.h>
#include <cstddef>

// GroupedESNCell: T=4096 sequential steps; per step 8 matvecs (2048x2048),
// per-group norm, leaky normalized update.
//
// Persistent kernel, 128 CTAs (16 per group), one custom grid barrier per step.
// Each CTA owns 128 output rows of one group, keeps the full group hidden
// state (2048 floats) redundantly in shared memory, so after the single
// barrier it can rebuild h_new locally from the global `pre` buffer.

#define G 8
#define H 2048
#define T_STEPS 4096
#define NCTA 128
#define CTAS_PER_GROUP (NCTA / G)           // 16
#define ROWS_PER_CTA (H / CTAS_PER_GROUP)   // 128
#define THREADS 256
#define NWARPS (THREADS / 32)               // 8
#define ROWS_PER_WARP (ROWS_PER_CTA / NWARPS) // 16
#define RADIUS_F 100.0f
#define LEAKY_F 1.0f
#define K4 (H / (4 * 32))                   // 16 float4 chunks per lane per row

// Global scratch (allocation-free): double-buffered by step parity.
__device__ float g_pre[2][G * H];
__device__ float g_psq[2][NCTA];
__device__ unsigned int g_cnt = 0;
__device__ unsigned int g_epoch = 0;

__global__ __launch_bounds__(THREADS, 1)
void esn_persistent_kernel(const float* __restrict__ x,
                           const float* __restrict__ W_ih,
                           const float* __restrict__ W_hh,
                           float* __restrict__ out)
{
    __shared__ float h_sh[H];            // full group hidden state
    __shared__ float x_sh[T_STEPS];      // whole input sequence (16 KB)
    __shared__ float wih_sh[ROWS_PER_CTA];
    __shared__ float red_sh[NWARPS];
    __shared__ float coef_sh;

    const int tid  = threadIdx.x;
    const int cta  = blockIdx.x;
    const int g    = cta / CTAS_PER_GROUP;
    const int sub  = cta % CTAS_PER_GROUP;
    const int rowbase = sub * ROWS_PER_CTA;
    const int warp = tid >> 5;
    const int lane = tid & 31;

    const float lr   = (LEAKY_F * (float)(G - g)) / (float)G;
    const float leak = 1.0f - lr;

    const float* Wg = W_hh + (size_t)g * H * H;
    const float4* hs4 = (const float4*)h_sh;

    // ---- init shared state ----
    for (int i = tid; i < H; i += THREADS) h_sh[i] = 0.0f;
    for (int i = tid; i < T_STEPS; i += THREADS) x_sh[i] = x[i];
    if (tid < ROWS_PER_CTA) wih_sh[tid] = W_ih[rowbase + tid];
    __syncthreads();

    for (int t = 0; t < T_STEPS; ++t) {
        const int par = t & 1;
        const float xt = x_sh[t];

        // ================= Phase A: matvec for my 128 rows =================
        float warp_sq = 0.0f;
        const int wrow0 = rowbase + warp * ROWS_PER_WARP;

        #pragma unroll 1
        for (int r = 0; r < ROWS_PER_WARP; r += 2) {
            const int i0 = wrow0 + r;
            const float4* w0 = (const float4*)(Wg + (size_t)i0 * H);
            const float4* w1 = (const float4*)(Wg + (size_t)(i0 + 1) * H);
            float a0 = 0.0f, a1 = 0.0f;
            #pragma unroll
            for (int k = 0; k < K4; ++k) {
                const int idx = lane + 32 * k;
                float4 hv = hs4[idx];
                float4 v0 = w0[idx];
                float4 v1 = w1[idx];
                a0 += v0.x * hv.x + v0.y * hv.y + v0.z * hv.z + v0.w * hv.w;
                a1 += v1.x * hv.x + v1.y * hv.y + v1.z * hv.z + v1.w * hv.w;
            }
            #pragma unroll
            for (int s = 16; s > 0; s >>= 1) {
                a0 += __shfl_xor_sync(0xffffffffu, a0, s);
                a1 += __shfl_xor_sync(0xffffffffu, a1, s);
            }
            const float pre0 = a0 + xt * wih_sh[i0 - rowbase];
            const float pre1 = a1 + xt * wih_sh[i0 + 1 - rowbase];
            if (lane == 0) {
                float2 p2 = make_float2(pre0, pre1);
                // L2-only store: other CTAs read this after the barrier
                __stcg((float2*)&g_pre[par][g * H + i0], p2);
                warp_sq += pre0 * pre0 + pre1 * pre1;
            }
        }
        if (lane == 0) red_sh[warp] = warp_sq;
        __syncthreads();
        if (tid == 0) {
            float s = 0.0f;
            #pragma unroll
            for (int w = 0; w < NWARPS; ++w) s += red_sh[w];
            __stcg(&g_psq[par][cta], s);
        }

        // ================= Grid barrier (one per step) =================
        __threadfence();  // cumulative release of this CTA's g_pre/g_psq
        if (tid == 0) {
            volatile unsigned int* ve = (volatile unsigned int*)&g_epoch;
            const unsigned int snap = *ve;        // snapshot before arriving
            const unsigned int old = atomicAdd(&g_cnt, 1u);
            if (old == NCTA - 1u) {
                g_cnt = 0u;                        // safe: next arrivals gated on epoch
                __threadfence();
                atomicAdd(&g_epoch, 1u);
            } else {
                while (*ve == snap) { }
            }
        }
        __syncthreads();
        __threadfence();  // acquire side

        // ================= Phase B: norm + state update (redundant per CTA) ====
        if (tid == 0) {
            float s = 0.0f;
            #pragma unroll
            for (int c = 0; c < CTAS_PER_GROUP; ++c)
                s += __ldcg(&g_psq[par][g * CTAS_PER_GROUP + c]);
            coef_sh = lr * RADIUS_F * rsqrtf(s);
        }
        __syncthreads();
        const float cb = coef_sh;
        const float4* preg = (const float4*)&g_pre[par][g * H];
        float4* hmut = (float4*)h_sh;
        #pragma unroll
        for (int k = 0; k < H / (4 * THREADS); ++k) {   // 2 iterations
            const int idx = tid + THREADS * k;
            float4 p  = __ldcg(&preg[idx]);             // bypass L1 (stale-line safety)
            float4 hv = hmut[idx];
            hv.x = leak * hv.x + cb * p.x;
            hv.y = leak * hv.y + cb * p.y;
            hv.z = leak * hv.z + cb * p.z;
            hv.w = leak * hv.w + cb * p.w;
            hmut[idx] = hv;
        }
        __syncthreads();

        // write my slice of the output row (each element written exactly once)
        if (tid < ROWS_PER_CTA) {
            out[(size_t)t * (G * H) + (size_t)g * H + rowbase + tid] =
                h_sh[rowbase + tid];
        }
        // no extra sync needed: Phase A next step only READS h_sh; the next
        // Phase-B write to h_sh is gated by the next grid barrier + syncthreads.
    }
}

extern "C" void kernel_launch(void* const* d_in, const int* in_sizes, int n_in,
                              void* d_out, int out_size)
{
    const float* x    = (const float*)d_in[0];   // [T, 1]
    const float* W_ih = (const float*)d_in[1];   // [H, 1]
    const float* W_hh = (const float*)d_in[2];   // [G, H, H]
    float* out = (float*)d_out;                  // [T, G*H]

    esn_persistent_kernel<<<NCTA, THREADS>>>(x, W_ih, W_hh, out);
}

// round 5
// speedup vs baseline: 1.6556x; 1.6442x over previous
#include <cuda_runtime.h>
#include <cstddef>

// GroupedESNCell, round 4: W_hh quantized to int16 + int4 residual (2.5 B/elem,
// 84 MB total -> L2-resident). Main dot: fp32 h, PRMT magic dequant. Residual
// dot: DP4A against per-step int8-quantized h. Persistent kernel, one grid
// barrier per step.

#define G 8
#define H 2048
#define T_STEPS 4096
#define NCTA 128
#define CTAS_PER_GROUP (NCTA / G)             // 16
#define ROWS_PER_CTA (H / CTAS_PER_GROUP)     // 128
#define THREADS 256
#define NWARPS (THREADS / 32)                 // 8
#define ROWS_PER_WARP (ROWS_PER_CTA / NWARPS) // 16
#define RADIUS_F 100.0f
#define LEAKY_F 1.0f
#define NROWS_TOTAL (G * H)                   // 16384
#define MAGIC_F 8421376.0f                    // 2^23 + 32768
#define NGRP 256                              // column groups per row (8 cols each)

// ---- global scratch (allocation-free) ----
// q16 weights, split layout: per row, uint4 group i = cols {4i..4i+3, 4i+1024..4i+1027}
__device__ unsigned int g_wq[(size_t)G * H * H / 2];   // 67 MB
// q4 residuals: u32 group i = 8 nibbles, same column set/order as above
__device__ unsigned int g_wr[(size_t)G * H * H / 8];   // 16.8 MB
__device__ float g_step[NROWS_TOTAL];
__device__ float g_pre[2][G * H];
__device__ float g_psq[2][NCTA];
__device__ unsigned int g_cnt = 0;
__device__ unsigned int g_epoch = 0;

// ============================================================================
// Kernel A: per-row max|w| -> step = rowmax/32767 (one warp per row)
// ============================================================================
__global__ void rowscale_kernel(const float* __restrict__ W_hh)
{
    const int warp = threadIdx.x >> 5;
    const int lane = threadIdx.x & 31;
    const int row  = blockIdx.x * 8 + warp;
    const float* w = W_hh + (size_t)row * H;

    float m = 0.0f;
    #pragma unroll
    for (int k = 0; k < H / 32; ++k)
        m = fmaxf(m, fabsf(w[lane + 32 * k]));
    #pragma unroll
    for (int s = 16; s > 0; s >>= 1)
        m = fmaxf(m, __shfl_xor_sync(0xffffffffu, m, s));
    if (lane == 0)
        g_step[row] = fmaxf(m, 1e-30f) * (1.0f / 32767.0f);
}

// ============================================================================
// Kernel B: quantize. One thread per (row, group): 8 elements ->
//   uint4 of biased-u16 pairs + one u32 of 8 signed nibbles (residual)
// ============================================================================
__global__ void quantize_kernel(const float* __restrict__ W_hh)
{
    const int gid = blockIdx.x * blockDim.x + threadIdx.x;
    if (gid >= NROWS_TOTAL * NGRP) return;
    const int row = gid >> 8;
    const int i   = gid & (NGRP - 1);
    const float* wr = W_hh + (size_t)row * H;
    const float inv = 1.0f / g_step[row];

    float4 wa = *(const float4*)(wr + 4 * i);
    float4 wb = *(const float4*)(wr + 4 * i + 1024);
    float v[8] = {wa.x, wa.y, wa.z, wa.w, wb.x, wb.y, wb.z, wb.w};

    unsigned int u16v[8];
    unsigned int nib = 0;
    #pragma unroll
    for (int j = 0; j < 8; ++j) {
        float s = v[j] * inv;
        int q = __float2int_rn(s);
        q = min(max(q, -32767), 32767);
        float r = s - (float)q;                 // [-0.5, 0.5]
        int q4 = __float2int_rn(r * 16.0f);
        q4 = min(max(q4, -8), 7);
        u16v[j] = (unsigned int)(q + 32768);
        nib |= (unsigned int)(q4 & 0xF) << (4 * j);
    }
    uint4 qs;
    qs.x = u16v[0] | (u16v[1] << 16);
    qs.y = u16v[2] | (u16v[3] << 16);
    qs.z = u16v[4] | (u16v[5] << 16);
    qs.w = u16v[6] | (u16v[7] << 16);
    ((uint4*)g_wq)[(size_t)row * NGRP + i] = qs;
    g_wr[(size_t)row * NGRP + i] = nib;
}

// ---- dequant helpers: biased u16 -> float q16 value ----
__device__ __forceinline__ float cvt_lo(unsigned int p)
{
    unsigned int r;
    asm("prmt.b32 %0, %1, %2, 0x7610;" : "=r"(r) : "r"(p), "r"(0x4B000000u));
    return __uint_as_float(r) - MAGIC_F;
}
__device__ __forceinline__ float cvt_hi(unsigned int p)
{
    unsigned int r;
    asm("prmt.b32 %0, %1, %2, 0x7632;" : "=r"(r) : "r"(p), "r"(0x4B000000u));
    return __uint_as_float(r) - MAGIC_F;
}
__device__ __forceinline__ unsigned int pack4(int a, int b, int c, int d)
{
    return (a & 0xFF) | ((b & 0xFF) << 8) | ((c & 0xFF) << 16) | ((d & 0xFF) << 24);
}

// ============================================================================
// Persistent recurrence kernel
// ============================================================================
__global__ __launch_bounds__(THREADS, 1)
void esn_persistent_kernel(const float* __restrict__ x,
                           const float* __restrict__ W_ih,
                           float* __restrict__ out)
{
    __shared__ float h_sh[H];
    __shared__ uint2 hs8_sh[NGRP];           // packed int8 h (even/odd byte groups)
    __shared__ float x_sh[T_STEPS];
    __shared__ float wih_sh[ROWS_PER_CTA];
    __shared__ float step_sh[ROWS_PER_CTA];
    __shared__ float red_sh[NWARPS];
    __shared__ float coef_sh;
    __shared__ float hstep256_sh;            // (hmax/127)/256
    __shared__ float invh_sh;                // 127/hmax (0 if hmax==0)

    const int tid  = threadIdx.x;
    const int cta  = blockIdx.x;
    const int g    = cta / CTAS_PER_GROUP;
    const int sub  = cta % CTAS_PER_GROUP;
    const int rowbase = sub * ROWS_PER_CTA;
    const int warp = tid >> 5;
    const int lane = tid & 31;

    const float lr   = (LEAKY_F * (float)(G - g)) / (float)G;
    const float leak = 1.0f - lr;

    const uint4* Wq = (const uint4*)g_wq + (size_t)g * H * NGRP;   // per-group base
    const unsigned int* Wr = g_wr + (size_t)g * H * NGRP;
    const float4* hs4 = (const float4*)h_sh;

    for (int i = tid; i < H; i += THREADS) h_sh[i] = 0.0f;
    for (int i = tid; i < NGRP; i += THREADS) hs8_sh[i] = make_uint2(0u, 0u);
    for (int i = tid; i < T_STEPS; i += THREADS) x_sh[i] = x[i];
    if (tid < ROWS_PER_CTA) {
        wih_sh[tid]  = W_ih[rowbase + tid];
        step_sh[tid] = g_step[g * H + rowbase + tid];
    }
    if (tid == 0) { hstep256_sh = 0.0f; invh_sh = 0.0f; }
    __syncthreads();

    for (int t = 0; t < T_STEPS; ++t) {
        const int par = t & 1;
        const float xt = x_sh[t];
        const float hstep256 = hstep256_sh;

        // ============ Phase A: quantized matvec for my 128 rows =============
        float warp_sq = 0.0f;
        const int wrow0 = rowbase + warp * ROWS_PER_WARP;

        #pragma unroll 1
        for (int r = 0; r < ROWS_PER_WARP; r += 2) {
            const int r0 = wrow0 + r;
            const uint4* wq0 = Wq + (size_t)r0 * NGRP;
            const uint4* wq1 = Wq + (size_t)(r0 + 1) * NGRP;
            const unsigned int* wr0 = Wr + (size_t)r0 * NGRP;
            const unsigned int* wr1 = Wr + (size_t)(r0 + 1) * NGRP;

            float a0 = 0.0f, a1 = 0.0f;
            int dp0 = 0, dp1 = 0;
            #pragma unroll 4
            for (int k = 0; k < 8; ++k) {
                const int i = lane + 32 * k;
                float4 h0 = hs4[i];
                float4 h1 = hs4[i + 256];
                uint2  hp = hs8_sh[i];

                uint4 qa = __ldcg(&wq0[i]);
                uint4 qb = __ldcg(&wq1[i]);
                unsigned int x0 = __ldcg(&wr0[i]);
                unsigned int x1 = __ldcg(&wr1[i]);

                a0 += cvt_lo(qa.x) * h0.x + cvt_hi(qa.x) * h0.y
                    + cvt_lo(qa.y) * h0.z + cvt_hi(qa.y) * h0.w
                    + cvt_lo(qa.z) * h1.x + cvt_hi(qa.z) * h1.y
                    + cvt_lo(qa.w) * h1.z + cvt_hi(qa.w) * h1.w;
                a1 += cvt_lo(qb.x) * h0.x + cvt_hi(qb.x) * h0.y
                    + cvt_lo(qb.y) * h0.z + cvt_hi(qb.y) * h0.w
                    + cvt_lo(qb.z) * h1.x + cvt_hi(qb.z) * h1.y
                    + cvt_lo(qb.w) * h1.z + cvt_hi(qb.w) * h1.w;

                int ea = (int)((x0 << 4) & 0xF0F0F0F0u);   // even cols: 16*q4 as s8
                int oa = (int)(x0 & 0xF0F0F0F0u);          // odd cols
                int eb = (int)((x1 << 4) & 0xF0F0F0F0u);
                int ob = (int)(x1 & 0xF0F0F0F0u);
                dp0 = __dp4a(ea, (int)hp.x, dp0);
                dp0 = __dp4a(oa, (int)hp.y, dp0);
                dp1 = __dp4a(eb, (int)hp.x, dp1);
                dp1 = __dp4a(ob, (int)hp.y, dp1);
            }
            // fold residual (exact int -> float, |dp| < 2^24) then warp-reduce
            float v0 = fmaf(hstep256, (float)dp0, a0);
            float v1 = fmaf(hstep256, (float)dp1, a1);
            #pragma unroll
            for (int s = 16; s > 0; s >>= 1) {
                v0 += __shfl_xor_sync(0xffffffffu, v0, s);
                v1 += __shfl_xor_sync(0xffffffffu, v1, s);
            }
            if (lane == 0) {
                const float pre0 = fmaf(step_sh[r0 - rowbase], v0,
                                        xt * wih_sh[r0 - rowbase]);
                const float pre1 = fmaf(step_sh[r0 + 1 - rowbase], v1,
                                        xt * wih_sh[r0 + 1 - rowbase]);
                __stcg((float2*)&g_pre[par][g * H + r0], make_float2(pre0, pre1));
                warp_sq += pre0 * pre0 + pre1 * pre1;
            }
        }
        if (lane == 0) red_sh[warp] = warp_sq;
        __syncthreads();
        if (tid == 0) {
            float s = 0.0f;
            #pragma unroll
            for (int w = 0; w < NWARPS; ++w) s += red_sh[w];
            __stcg(&g_psq[par][cta], s);
        }

        // ==================== grid barrier (one per step) ===================
        __threadfence();
        if (tid == 0) {
            volatile unsigned int* ve = (volatile unsigned int*)&g_epoch;
            const unsigned int snap = *ve;
            const unsigned int old = atomicAdd(&g_cnt, 1u);
            if (old == NCTA - 1u) {
                g_cnt = 0u;
                __threadfence();
                atomicAdd(&g_epoch, 1u);
            } else {
                while (*ve == snap) { }
            }
        }
        __syncthreads();
        __threadfence();

        // ============ Phase B: norm + state update + h8 repack ==============
        if (tid == 0) {
            float s = 0.0f;
            #pragma unroll
            for (int c = 0; c < CTAS_PER_GROUP; ++c)
                s += __ldcg(&g_psq[par][g * CTAS_PER_GROUP + c]);
            coef_sh = lr * RADIUS_F * rsqrtf(s);
        }
        __syncthreads();
        const float cb = coef_sh;
        const float4* preg = (const float4*)&g_pre[par][g * H];
        float4* hmut = (float4*)h_sh;
        float m = 0.0f;
        #pragma unroll
        for (int k = 0; k < H / (4 * THREADS); ++k) {   // 2 iterations
            const int idx = tid + THREADS * k;
            float4 p  = __ldcg(&preg[idx]);
            float4 hv = hmut[idx];
            hv.x = leak * hv.x + cb * p.x;
            hv.y = leak * hv.y + cb * p.y;
            hv.z = leak * hv.z + cb * p.z;
            hv.w = leak * hv.w + cb * p.w;
            hmut[idx] = hv;
            m = fmaxf(m, fmaxf(fmaxf(fabsf(hv.x), fabsf(hv.y)),
                               fmaxf(fabsf(hv.z), fabsf(hv.w))));
        }
        #pragma unroll
        for (int s = 16; s > 0; s >>= 1)
            m = fmaxf(m, __shfl_xor_sync(0xffffffffu, m, s));
        if (lane == 0) red_sh[warp] = m;
        __syncthreads();                    // h writes + per-warp maxes visible
        if (tid == 0) {
            float mm = 0.0f;
            #pragma unroll
            for (int w = 0; w < NWARPS; ++w) mm = fmaxf(mm, red_sh[w]);
            const float hstep = mm * (1.0f / 127.0f);
            hstep256_sh = hstep * (1.0f / 256.0f);
            invh_sh = (mm > 0.0f) ? 127.0f / mm : 0.0f;
        }
        __syncthreads();
        // pack h8: thread t handles group t (cols 4t..4t+3, 4t+1024..4t+1027)
        {
            const float inv = invh_sh;
            float4 ha = hs4[tid];
            float4 hb = hs4[tid + 256];
            int q0 = __float2int_rn(ha.x * inv);
            int q1 = __float2int_rn(ha.y * inv);
            int q2 = __float2int_rn(ha.z * inv);
            int q3 = __float2int_rn(ha.w * inv);
            int q4 = __float2int_rn(hb.x * inv);
            int q5 = __float2int_rn(hb.y * inv);
            int q6 = __float2int_rn(hb.z * inv);
            int q7 = __float2int_rn(hb.w * inv);
            hs8_sh[tid] = make_uint2(pack4(q0, q2, q4, q6),
                                     pack4(q1, q3, q5, q7));
        }
        // output slice (streaming store, keep L2 for weights)
        if (tid < ROWS_PER_CTA) {
            __stcs(&out[(size_t)t * (G * H) + (size_t)g * H + rowbase + tid],
                   h_sh[rowbase + tid]);
        }
        __syncthreads();
    }
}

extern "C" void kernel_launch(void* const* d_in, const int* in_sizes, int n_in,
                              void* d_out, int out_size)
{
    const float* x    = (const float*)d_in[0];   // [T, 1]
    const float* W_ih = (const float*)d_in[1];   // [H, 1]
    const float* W_hh = (const float*)d_in[2];   // [G, H, H]
    float* out = (float*)d_out;                  // [T, G*H]

    rowscale_kernel<<<NROWS_TOTAL / 8, 256>>>(W_hh);
    quantize_kernel<<<(NROWS_TOTAL * NGRP + 255) / 256, 256>>>(W_hh);
    esn_persistent_kernel<<<NCTA, THREADS>>>(x, W_ih, out);
}

// round 6
// speedup vs baseline: 2.2193x; 1.3405x over previous
#include <cuda_runtime.h>
#include <cstddef>

// GroupedESNCell, round 5: same int16+int4 quantization as R4 (passed,
// rel_err 4e-5), throughput rework:
//   - 512 threads/CTA (4 warps/SMSP) for latency hiding
//   - 4 rows per inner iteration sharing h loads
//   - packed f32x2 dequant math (add.rn.f32x2 / fma.rn.f32x2)

#define G 8
#define H 2048
#define T_STEPS 4096
#define NCTA 128
#define CTAS_PER_GROUP (NCTA / G)             // 16
#define ROWS_PER_CTA (H / CTAS_PER_GROUP)     // 128
#define THREADS 512
#define NWARPS (THREADS / 32)                 // 16
#define ROWS_PER_WARP (ROWS_PER_CTA / NWARPS) // 8
#define RADIUS_F 100.0f
#define LEAKY_F 1.0f
#define NROWS_TOTAL (G * H)                   // 16384
#define MAGIC_F 8421376.0f                    // 2^23 + 32768
#define NGRP 256                              // column groups per row (8 cols each)

// ---- global scratch (allocation-free) ----
// q16 weights, split layout: per row, uint4 group i = cols {4i..4i+3, 4i+1024..4i+1027}
__device__ unsigned int g_wq[(size_t)G * H * H / 2];   // 67 MB
// q4 residuals: u32 group i = 8 nibbles, same column set/order
__device__ unsigned int g_wr[(size_t)G * H * H / 8];   // 16.8 MB
__device__ float g_step[NROWS_TOTAL];
__device__ float g_pre[2][G * H];
__device__ float g_psq[2][NCTA];
__device__ unsigned int g_cnt = 0;
__device__ unsigned int g_epoch = 0;

// ============================================================================
// Prep kernel A: per-row max|w| -> step = rowmax/32767 (one warp per row)
// ============================================================================
__global__ void rowscale_kernel(const float* __restrict__ W_hh)
{
    const int warp = threadIdx.x >> 5;
    const int lane = threadIdx.x & 31;
    const int row  = blockIdx.x * 8 + warp;
    const float* w = W_hh + (size_t)row * H;

    float m = 0.0f;
    #pragma unroll
    for (int k = 0; k < H / 32; ++k)
        m = fmaxf(m, fabsf(w[lane + 32 * k]));
    #pragma unroll
    for (int s = 16; s > 0; s >>= 1)
        m = fmaxf(m, __shfl_xor_sync(0xffffffffu, m, s));
    if (lane == 0)
        g_step[row] = fmaxf(m, 1e-30f) * (1.0f / 32767.0f);
}

// ============================================================================
// Prep kernel B: quantize. One thread per (row, group): 8 elements ->
//   uint4 of biased-u16 pairs + u32 of 8 signed nibbles (residual)
// ============================================================================
__global__ void quantize_kernel(const float* __restrict__ W_hh)
{
    const int gid = blockIdx.x * blockDim.x + threadIdx.x;
    if (gid >= NROWS_TOTAL * NGRP) return;
    const int row = gid >> 8;
    const int i   = gid & (NGRP - 1);
    const float* wr = W_hh + (size_t)row * H;
    const float inv = 1.0f / g_step[row];

    float4 wa = *(const float4*)(wr + 4 * i);
    float4 wb = *(const float4*)(wr + 4 * i + 1024);
    float v[8] = {wa.x, wa.y, wa.z, wa.w, wb.x, wb.y, wb.z, wb.w};

    unsigned int u16v[8];
    unsigned int nib = 0;
    #pragma unroll
    for (int j = 0; j < 8; ++j) {
        float s = v[j] * inv;
        int q = __float2int_rn(s);
        q = min(max(q, -32767), 32767);
        float r = s - (float)q;
        int q4 = __float2int_rn(r * 16.0f);
        q4 = min(max(q4, -8), 7);
        u16v[j] = (unsigned int)(q + 32768);
        nib |= (unsigned int)(q4 & 0xF) << (4 * j);
    }
    uint4 qs;
    qs.x = u16v[0] | (u16v[1] << 16);
    qs.y = u16v[2] | (u16v[3] << 16);
    qs.z = u16v[4] | (u16v[5] << 16);
    qs.w = u16v[6] | (u16v[7] << 16);
    ((uint4*)g_wq)[(size_t)row * NGRP + i] = qs;
    g_wr[(size_t)row * NGRP + i] = nib;
}

// ============================================================================
// packed-f32 helpers (sm_100+ f32x2 pipe ops)
// ============================================================================
__device__ __forceinline__ float2 add2(float2 a, float2 b)
{
    float2 d;
    asm("{\n\t.reg .b64 ra, rb;\n\t"
        "mov.b64 ra, {%2, %3};\n\t"
        "mov.b64 rb, {%4, %5};\n\t"
        "add.rn.f32x2 ra, ra, rb;\n\t"
        "mov.b64 {%0, %1}, ra;\n\t}"
        : "=f"(d.x), "=f"(d.y)
        : "f"(a.x), "f"(a.y), "f"(b.x), "f"(b.y));
    return d;
}
__device__ __forceinline__ float2 fma2(float2 a, float2 b, float2 c)
{
    float2 d;
    asm("{\n\t.reg .b64 ra, rb, rc;\n\t"
        "mov.b64 ra, {%2, %3};\n\t"
        "mov.b64 rb, {%4, %5};\n\t"
        "mov.b64 rc, {%6, %7};\n\t"
        "fma.rn.f32x2 rc, ra, rb, rc;\n\t"
        "mov.b64 {%0, %1}, rc;\n\t}"
        : "=f"(d.x), "=f"(d.y)
        : "f"(a.x), "f"(a.y), "f"(b.x), "f"(b.y), "f"(c.x), "f"(c.y));
    return d;
}
// dequant a packed pair of biased u16 -> float2 of centered q16 values
__device__ __forceinline__ float2 dq2(unsigned int p)
{
    unsigned int lo, hi;
    asm("prmt.b32 %0, %1, %2, 0x7610;" : "=r"(lo) : "r"(p), "r"(0x4B000000u));
    asm("prmt.b32 %0, %1, %2, 0x7632;" : "=r"(hi) : "r"(p), "r"(0x4B000000u));
    return add2(make_float2(__uint_as_float(lo), __uint_as_float(hi)),
                make_float2(-MAGIC_F, -MAGIC_F));
}
__device__ __forceinline__ unsigned int pack4(int a, int b, int c, int d)
{
    return (a & 0xFF) | ((b & 0xFF) << 8) | ((c & 0xFF) << 16) | ((d & 0xFF) << 24);
}

// main-dot accumulate for one row's uint4 (8 cols) against h0/h1 float4s
__device__ __forceinline__ void acc_row(float2& acc, uint4 q,
                                        const float4& h0, const float4& h1)
{
    acc = fma2(dq2(q.x), make_float2(h0.x, h0.y), acc);
    acc = fma2(dq2(q.y), make_float2(h0.z, h0.w), acc);
    acc = fma2(dq2(q.z), make_float2(h1.x, h1.y), acc);
    acc = fma2(dq2(q.w), make_float2(h1.z, h1.w), acc);
}
// residual accumulate for one row's nibble-u32 against packed h8
__device__ __forceinline__ void acc_res(int& dp, unsigned int x, uint2 hp)
{
    int e = (int)((x << 4) & 0xF0F0F0F0u);   // even cols: 16*q4 as s8
    int o = (int)(x & 0xF0F0F0F0u);          // odd cols
    dp = __dp4a(e, (int)hp.x, dp);
    dp = __dp4a(o, (int)hp.y, dp);
}

// ============================================================================
// Persistent recurrence kernel
// ============================================================================
__global__ __launch_bounds__(THREADS, 1)
void esn_persistent_kernel(const float* __restrict__ x,
                           const float* __restrict__ W_ih,
                           float* __restrict__ out)
{
    __shared__ float h_sh[H];
    __shared__ uint2 hs8_sh[NGRP];           // packed int8 h (even/odd byte groups)
    __shared__ float x_sh[T_STEPS];
    __shared__ float wih_sh[ROWS_PER_CTA];
    __shared__ float step_sh[ROWS_PER_CTA];
    __shared__ float red_sh[NWARPS];
    __shared__ float coef_sh;
    __shared__ float hstep256_sh;            // (hmax/127)/256
    __shared__ float invh_sh;                // 127/hmax

    const int tid  = threadIdx.x;
    const int cta  = blockIdx.x;
    const int g    = cta / CTAS_PER_GROUP;
    const int sub  = cta % CTAS_PER_GROUP;
    const int rowbase = sub * ROWS_PER_CTA;
    const int warp = tid >> 5;
    const int lane = tid & 31;

    const float lr   = (LEAKY_F * (float)(G - g)) / (float)G;
    const float leak = 1.0f - lr;

    const uint4* Wq = (const uint4*)g_wq + (size_t)g * H * NGRP;
    const unsigned int* Wr = g_wr + (size_t)g * H * NGRP;
    const float4* hs4 = (const float4*)h_sh;

    for (int i = tid; i < H; i += THREADS) h_sh[i] = 0.0f;
    for (int i = tid; i < NGRP; i += THREADS) hs8_sh[i] = make_uint2(0u, 0u);
    for (int i = tid; i < T_STEPS; i += THREADS) x_sh[i] = x[i];
    if (tid < ROWS_PER_CTA) {
        wih_sh[tid]  = W_ih[rowbase + tid];
        step_sh[tid] = g_step[g * H + rowbase + tid];
    }
    if (tid == 0) { hstep256_sh = 0.0f; invh_sh = 0.0f; }
    __syncthreads();

    for (int t = 0; t < T_STEPS; ++t) {
        const int par = t & 1;
        const float xt = x_sh[t];
        const float hstep256 = hstep256_sh;

        // ============ Phase A: quantized matvec, 8 rows per warp ============
        float warp_sq = 0.0f;
        const int wrow0 = rowbase + warp * ROWS_PER_WARP;

        #pragma unroll 1
        for (int rr = 0; rr < ROWS_PER_WARP; rr += 4) {
            const int r0 = wrow0 + rr;
            const uint4* wqb = Wq + (size_t)r0 * NGRP;       // rows at +NGRP steps
            const unsigned int* wrb = Wr + (size_t)r0 * NGRP;

            float2 a0 = make_float2(0.f, 0.f), a1 = a0, a2 = a0, a3 = a0;
            int dp0 = 0, dp1 = 0, dp2 = 0, dp3 = 0;

            #pragma unroll 2
            for (int k = 0; k < 8; ++k) {
                const int i = lane + 32 * k;
                float4 h0 = hs4[i];
                float4 h1 = hs4[i + 256];
                uint2  hp = hs8_sh[i];

                uint4 qa = __ldcg(&wqb[i]);
                uint4 qb = __ldcg(&wqb[i + NGRP]);
                uint4 qc = __ldcg(&wqb[i + 2 * NGRP]);
                uint4 qd = __ldcg(&wqb[i + 3 * NGRP]);
                unsigned int xa = __ldcg(&wrb[i]);
                unsigned int xb = __ldcg(&wrb[i + NGRP]);
                unsigned int xc = __ldcg(&wrb[i + 2 * NGRP]);
                unsigned int xd = __ldcg(&wrb[i + 3 * NGRP]);

                acc_row(a0, qa, h0, h1);
                acc_row(a1, qb, h0, h1);
                acc_row(a2, qc, h0, h1);
                acc_row(a3, qd, h0, h1);
                acc_res(dp0, xa, hp);
                acc_res(dp1, xb, hp);
                acc_res(dp2, xc, hp);
                acc_res(dp3, xd, hp);
            }
            float v0 = fmaf(hstep256, (float)dp0, a0.x + a0.y);
            float v1 = fmaf(hstep256, (float)dp1, a1.x + a1.y);
            float v2 = fmaf(hstep256, (float)dp2, a2.x + a2.y);
            float v3 = fmaf(hstep256, (float)dp3, a3.x + a3.y);
            #pragma unroll
            for (int s = 16; s > 0; s >>= 1) {
                v0 += __shfl_xor_sync(0xffffffffu, v0, s);
                v1 += __shfl_xor_sync(0xffffffffu, v1, s);
                v2 += __shfl_xor_sync(0xffffffffu, v2, s);
                v3 += __shfl_xor_sync(0xffffffffu, v3, s);
            }
            if (lane == 0) {
                const int lr0 = r0 - rowbase;
                const float p0 = fmaf(step_sh[lr0],     v0, xt * wih_sh[lr0]);
                const float p1 = fmaf(step_sh[lr0 + 1], v1, xt * wih_sh[lr0 + 1]);
                const float p2 = fmaf(step_sh[lr0 + 2], v2, xt * wih_sh[lr0 + 2]);
                const float p3 = fmaf(step_sh[lr0 + 3], v3, xt * wih_sh[lr0 + 3]);
                __stcg((float4*)&g_pre[par][g * H + r0],
                       make_float4(p0, p1, p2, p3));
                warp_sq += p0 * p0 + p1 * p1 + p2 * p2 + p3 * p3;
            }
        }
        if (lane == 0) red_sh[warp] = warp_sq;
        __syncthreads();
        if (tid == 0) {
            float s = 0.0f;
            #pragma unroll
            for (int w = 0; w < NWARPS; ++w) s += red_sh[w];
            __stcg(&g_psq[par][cta], s);
        }

        // ==================== grid barrier (one per step) ===================
        __threadfence();
        if (tid == 0) {
            volatile unsigned int* ve = (volatile unsigned int*)&g_epoch;
            const unsigned int snap = *ve;
            const unsigned int old = atomicAdd(&g_cnt, 1u);
            if (old == NCTA - 1u) {
                g_cnt = 0u;
                __threadfence();
                atomicAdd(&g_epoch, 1u);
            } else {
                while (*ve == snap) { }
            }
        }
        __syncthreads();
        __threadfence();

        // ============ Phase B: norm + state update + h8 repack ==============
        if (tid == 0) {
            float s = 0.0f;
            #pragma unroll
            for (int c = 0; c < CTAS_PER_GROUP; ++c)
                s += __ldcg(&g_psq[par][g * CTAS_PER_GROUP + c]);
            coef_sh = lr * RADIUS_F * rsqrtf(s);
        }
        __syncthreads();
        const float cb = coef_sh;
        const float4* preg = (const float4*)&g_pre[par][g * H];
        float4* hmut = (float4*)h_sh;
        float m = 0.0f;
        {
            const int idx = tid;                 // 512 threads x float4 = H
            float4 p  = __ldcg(&preg[idx]);
            float4 hv = hmut[idx];
            hv.x = leak * hv.x + cb * p.x;
            hv.y = leak * hv.y + cb * p.y;
            hv.z = leak * hv.z + cb * p.z;
            hv.w = leak * hv.w + cb * p.w;
            hmut[idx] = hv;
            m = fmaxf(fmaxf(fabsf(hv.x), fabsf(hv.y)),
                      fmaxf(fabsf(hv.z), fabsf(hv.w)));
        }
        #pragma unroll
        for (int s = 16; s > 0; s >>= 1)
            m = fmaxf(m, __shfl_xor_sync(0xffffffffu, m, s));
        if (lane == 0) red_sh[warp] = m;
        __syncthreads();
        if (tid == 0) {
            float mm = 0.0f;
            #pragma unroll
            for (int w = 0; w < NWARPS; ++w) mm = fmaxf(mm, red_sh[w]);
            const float hstep = mm * (1.0f / 127.0f);
            hstep256_sh = hstep * (1.0f / 256.0f);
            invh_sh = (mm > 0.0f) ? 127.0f / mm : 0.0f;
        }
        __syncthreads();
        // pack h8: threads 0..255 handle group tid
        if (tid < NGRP) {
            const float inv = invh_sh;
            float4 ha = hs4[tid];
            float4 hb = hs4[tid + 256];
            int q0 = __float2int_rn(ha.x * inv);
            int q1 = __float2int_rn(ha.y * inv);
            int q2 = __float2int_rn(ha.z * inv);
            int q3 = __float2int_rn(ha.w * inv);
            int q4 = __float2int_rn(hb.x * inv);
            int q5 = __float2int_rn(hb.y * inv);
            int q6 = __float2int_rn(hb.z * inv);
            int q7 = __float2int_rn(hb.w * inv);
            hs8_sh[tid] = make_uint2(pack4(q0, q2, q4, q6),
                                     pack4(q1, q3, q5, q7));
        }
        // output slice (streaming store, keep L2 for weights)
        if (tid < ROWS_PER_CTA) {
            __stcs(&out[(size_t)t * (G * H) + (size_t)g * H + rowbase + tid],
                   h_sh[rowbase + tid]);
        }
        __syncthreads();
    }
}

extern "C" void kernel_launch(void* const* d_in, const int* in_sizes, int n_in,
                              void* d_out, int out_size)
{
    const float* x    = (const float*)d_in[0];   // [T, 1]
    const float* W_ih = (const float*)d_in[1];   // [H, 1]
    const float* W_hh = (const float*)d_in[2];   // [G, H, H]
    float* out = (float*)d_out;                  // [T, G*H]

    rowscale_kernel<<<NROWS_TOTAL / 8, 256>>>(W_hh);
    quantize_kernel<<<(NROWS_TOTAL * NGRP + 255) / 256, 256>>>(W_hh);
    esn_persistent_kernel<<<NCTA, THREADS>>>(x, W_ih, out);
}

// round 7
// speedup vs baseline: 2.2480x; 1.0129x over previous
#include <cuda_runtime.h>
#include <cstddef>

// GroupedESNCell, round 6: numerics identical to R5 (int16+int4, rel_err 4e-5).
// Throughput changes:
//   - per-GROUP barriers (16 CTAs each) instead of one global 128-CTA barrier
//   - warps 0-3 load their 32 rows of weights via __ldca (L1-resident, ~160KB,
//     re-touched every step; all other weight loads are __ldcg so the resident
//     set is never evicted) -> 25% of weight traffic served from L1

#define G 8
#define H 2048
#define T_STEPS 4096
#define NCTA 128
#define CTAS_PER_GROUP (NCTA / G)             // 16
#define ROWS_PER_CTA (H / CTAS_PER_GROUP)     // 128
#define THREADS 512
#define NWARPS (THREADS / 32)                 // 16
#define ROWS_PER_WARP (ROWS_PER_CTA / NWARPS) // 8
#define RADIUS_F 100.0f
#define LEAKY_F 1.0f
#define NROWS_TOTAL (G * H)                   // 16384
#define MAGIC_F 8421376.0f                    // 2^23 + 32768
#define NGRP 256                              // column groups per row (8 cols each)
#define L1_WARPS 4                            // warps whose rows live in L1

// ---- global scratch (allocation-free) ----
__device__ unsigned int g_wq[(size_t)G * H * H / 2];   // 67 MB q16 (split layout)
__device__ unsigned int g_wr[(size_t)G * H * H / 8];   // 16.8 MB q4 residual
__device__ float g_step[NROWS_TOTAL];
__device__ float g_pre[2][G * H];
__device__ float g_psq[2][NCTA];
__device__ unsigned int g_cnt[G * 32];     // per-group arrival counter (padded)
__device__ unsigned int g_epoch[G * 32];   // per-group epoch (padded)

// ============================================================================
// Prep kernel A: per-row max|w| -> step = rowmax/32767 (one warp per row)
// ============================================================================
__global__ void rowscale_kernel(const float* __restrict__ W_hh)
{
    const int warp = threadIdx.x >> 5;
    const int lane = threadIdx.x & 31;
    const int row  = blockIdx.x * 8 + warp;
    const float* w = W_hh + (size_t)row * H;

    float m = 0.0f;
    #pragma unroll
    for (int k = 0; k < H / 32; ++k)
        m = fmaxf(m, fabsf(w[lane + 32 * k]));
    #pragma unroll
    for (int s = 16; s > 0; s >>= 1)
        m = fmaxf(m, __shfl_xor_sync(0xffffffffu, m, s));
    if (lane == 0)
        g_step[row] = fmaxf(m, 1e-30f) * (1.0f / 32767.0f);
}

// ============================================================================
// Prep kernel B: quantize. One thread per (row, group): 8 elements ->
//   uint4 of biased-u16 pairs + u32 of 8 signed nibbles (residual)
// layout per row: group i = cols {4i..4i+3, 4i+1024..4i+1027}
// ============================================================================
__global__ void quantize_kernel(const float* __restrict__ W_hh)
{
    const int gid = blockIdx.x * blockDim.x + threadIdx.x;
    if (gid >= NROWS_TOTAL * NGRP) return;
    const int row = gid >> 8;
    const int i   = gid & (NGRP - 1);
    const float* wr = W_hh + (size_t)row * H;
    const float inv = 1.0f / g_step[row];

    float4 wa = *(const float4*)(wr + 4 * i);
    float4 wb = *(const float4*)(wr + 4 * i + 1024);
    float v[8] = {wa.x, wa.y, wa.z, wa.w, wb.x, wb.y, wb.z, wb.w};

    unsigned int u16v[8];
    unsigned int nib = 0;
    #pragma unroll
    for (int j = 0; j < 8; ++j) {
        float s = v[j] * inv;
        int q = __float2int_rn(s);
        q = min(max(q, -32767), 32767);
        float r = s - (float)q;
        int q4 = __float2int_rn(r * 16.0f);
        q4 = min(max(q4, -8), 7);
        u16v[j] = (unsigned int)(q + 32768);
        nib |= (unsigned int)(q4 & 0xF) << (4 * j);
    }
    uint4 qs;
    qs.x = u16v[0] | (u16v[1] << 16);
    qs.y = u16v[2] | (u16v[3] << 16);
    qs.z = u16v[4] | (u16v[5] << 16);
    qs.w = u16v[6] | (u16v[7] << 16);
    ((uint4*)g_wq)[(size_t)row * NGRP + i] = qs;
    g_wr[(size_t)row * NGRP + i] = nib;
}

// ============================================================================
// packed-f32 helpers (sm_100+ f32x2 pipe ops)
// ============================================================================
__device__ __forceinline__ float2 add2(float2 a, float2 b)
{
    float2 d;
    asm("{\n\t.reg .b64 ra, rb;\n\t"
        "mov.b64 ra, {%2, %3};\n\t"
        "mov.b64 rb, {%4, %5};\n\t"
        "add.rn.f32x2 ra, ra, rb;\n\t"
        "mov.b64 {%0, %1}, ra;\n\t}"
        : "=f"(d.x), "=f"(d.y)
        : "f"(a.x), "f"(a.y), "f"(b.x), "f"(b.y));
    return d;
}
__device__ __forceinline__ float2 fma2(float2 a, float2 b, float2 c)
{
    float2 d;
    asm("{\n\t.reg .b64 ra, rb, rc;\n\t"
        "mov.b64 ra, {%2, %3};\n\t"
        "mov.b64 rb, {%4, %5};\n\t"
        "mov.b64 rc, {%6, %7};\n\t"
        "fma.rn.f32x2 rc, ra, rb, rc;\n\t"
        "mov.b64 {%0, %1}, rc;\n\t}"
        : "=f"(d.x), "=f"(d.y)
        : "f"(a.x), "f"(a.y), "f"(b.x), "f"(b.y), "f"(c.x), "f"(c.y));
    return d;
}
__device__ __forceinline__ float2 dq2(unsigned int p)
{
    unsigned int lo, hi;
    asm("prmt.b32 %0, %1, %2, 0x7610;" : "=r"(lo) : "r"(p), "r"(0x4B000000u));
    asm("prmt.b32 %0, %1, %2, 0x7632;" : "=r"(hi) : "r"(p), "r"(0x4B000000u));
    return add2(make_float2(__uint_as_float(lo), __uint_as_float(hi)),
                make_float2(-MAGIC_F, -MAGIC_F));
}
__device__ __forceinline__ unsigned int pack4(int a, int b, int c, int d)
{
    return (a & 0xFF) | ((b & 0xFF) << 8) | ((c & 0xFF) << 16) | ((d & 0xFF) << 24);
}
__device__ __forceinline__ void acc_row(float2& acc, uint4 q,
                                        const float4& h0, const float4& h1)
{
    acc = fma2(dq2(q.x), make_float2(h0.x, h0.y), acc);
    acc = fma2(dq2(q.y), make_float2(h0.z, h0.w), acc);
    acc = fma2(dq2(q.z), make_float2(h1.x, h1.y), acc);
    acc = fma2(dq2(q.w), make_float2(h1.z, h1.w), acc);
}
__device__ __forceinline__ void acc_res(int& dp, unsigned int x, uint2 hp)
{
    int e = (int)((x << 4) & 0xF0F0F0F0u);
    int o = (int)(x & 0xF0F0F0F0u);
    dp = __dp4a(e, (int)hp.x, dp);
    dp = __dp4a(o, (int)hp.y, dp);
}

// process one 4-row block (8 k-iters); USE_L1 selects __ldca vs __ldcg
template <bool USE_L1>
__device__ __forceinline__ void do_block4(
    const uint4* __restrict__ wqb, const unsigned int* __restrict__ wrb,
    const float4* __restrict__ hs4, const uint2* __restrict__ hs8,
    int lane, float hstep256,
    float& v0, float& v1, float& v2, float& v3)
{
    float2 a0 = make_float2(0.f, 0.f), a1 = a0, a2 = a0, a3 = a0;
    int dp0 = 0, dp1 = 0, dp2 = 0, dp3 = 0;

    #pragma unroll 2
    for (int k = 0; k < 8; ++k) {
        const int i = lane + 32 * k;
        float4 h0 = hs4[i];
        float4 h1 = hs4[i + 256];
        uint2  hp = hs8[i];

        uint4 qa, qb, qc, qd;
        unsigned int xa, xb, xc, xd;
        if (USE_L1) {
            qa = __ldca(&wqb[i]);
            qb = __ldca(&wqb[i + NGRP]);
            qc = __ldca(&wqb[i + 2 * NGRP]);
            qd = __ldca(&wqb[i + 3 * NGRP]);
            xa = __ldca(&wrb[i]);
            xb = __ldca(&wrb[i + NGRP]);
            xc = __ldca(&wrb[i + 2 * NGRP]);
            xd = __ldca(&wrb[i + 3 * NGRP]);
        } else {
            qa = __ldcg(&wqb[i]);
            qb = __ldcg(&wqb[i + NGRP]);
            qc = __ldcg(&wqb[i + 2 * NGRP]);
            qd = __ldcg(&wqb[i + 3 * NGRP]);
            xa = __ldcg(&wrb[i]);
            xb = __ldcg(&wrb[i + NGRP]);
            xc = __ldcg(&wrb[i + 2 * NGRP]);
            xd = __ldcg(&wrb[i + 3 * NGRP]);
        }

        acc_row(a0, qa, h0, h1);
        acc_row(a1, qb, h0, h1);
        acc_row(a2, qc, h0, h1);
        acc_row(a3, qd, h0, h1);
        acc_res(dp0, xa, hp);
        acc_res(dp1, xb, hp);
        acc_res(dp2, xc, hp);
        acc_res(dp3, xd, hp);
    }
    v0 = fmaf(hstep256, (float)dp0, a0.x + a0.y);
    v1 = fmaf(hstep256, (float)dp1, a1.x + a1.y);
    v2 = fmaf(hstep256, (float)dp2, a2.x + a2.y);
    v3 = fmaf(hstep256, (float)dp3, a3.x + a3.y);
}

// ============================================================================
// Persistent recurrence kernel
// ============================================================================
__global__ __launch_bounds__(THREADS, 1)
void esn_persistent_kernel(const float* __restrict__ x,
                           const float* __restrict__ W_ih,
                           float* __restrict__ out)
{
    __shared__ float h_sh[H];
    __shared__ uint2 hs8_sh[NGRP];
    __shared__ float x_sh[T_STEPS];
    __shared__ float wih_sh[ROWS_PER_CTA];
    __shared__ float step_sh[ROWS_PER_CTA];
    __shared__ float red_sh[NWARPS];
    __shared__ float coef_sh;
    __shared__ float hstep256_sh;
    __shared__ float invh_sh;

    const int tid  = threadIdx.x;
    const int cta  = blockIdx.x;
    const int g    = cta / CTAS_PER_GROUP;
    const int sub  = cta % CTAS_PER_GROUP;
    const int rowbase = sub * ROWS_PER_CTA;
    const int warp = tid >> 5;
    const int lane = tid & 31;

    const float lr   = (LEAKY_F * (float)(G - g)) / (float)G;
    const float leak = 1.0f - lr;

    const uint4* Wq = (const uint4*)g_wq + (size_t)g * H * NGRP;
    const unsigned int* Wr = g_wr + (size_t)g * H * NGRP;
    const float4* hs4 = (const float4*)h_sh;

    for (int i = tid; i < H; i += THREADS) h_sh[i] = 0.0f;
    for (int i = tid; i < NGRP; i += THREADS) hs8_sh[i] = make_uint2(0u, 0u);
    for (int i = tid; i < T_STEPS; i += THREADS) x_sh[i] = x[i];
    if (tid < ROWS_PER_CTA) {
        wih_sh[tid]  = W_ih[rowbase + tid];
        step_sh[tid] = g_step[g * H + rowbase + tid];
    }
    if (tid == 0) { hstep256_sh = 0.0f; invh_sh = 0.0f; }
    __syncthreads();

    unsigned int* const cntp = &g_cnt[g * 32];
    volatile unsigned int* const epop = (volatile unsigned int*)&g_epoch[g * 32];

    for (int t = 0; t < T_STEPS; ++t) {
        const int par = t & 1;
        const float xt = x_sh[t];
        const float hstep256 = hstep256_sh;

        // ============ Phase A: quantized matvec, 8 rows per warp ============
        float warp_sq = 0.0f;
        const int wrow0 = rowbase + warp * ROWS_PER_WARP;

        #pragma unroll 1
        for (int rr = 0; rr < ROWS_PER_WARP; rr += 4) {
            const int r0 = wrow0 + rr;
            const uint4* wqb = Wq + (size_t)r0 * NGRP;
            const unsigned int* wrb = Wr + (size_t)r0 * NGRP;

            float v0, v1, v2, v3;
            if (warp < L1_WARPS)
                do_block4<true >(wqb, wrb, hs4, hs8_sh, lane, hstep256,
                                 v0, v1, v2, v3);
            else
                do_block4<false>(wqb, wrb, hs4, hs8_sh, lane, hstep256,
                                 v0, v1, v2, v3);

            #pragma unroll
            for (int s = 16; s > 0; s >>= 1) {
                v0 += __shfl_xor_sync(0xffffffffu, v0, s);
                v1 += __shfl_xor_sync(0xffffffffu, v1, s);
                v2 += __shfl_xor_sync(0xffffffffu, v2, s);
                v3 += __shfl_xor_sync(0xffffffffu, v3, s);
            }
            if (lane == 0) {
                const int lr0 = r0 - rowbase;
                const float p0 = fmaf(step_sh[lr0],     v0, xt * wih_sh[lr0]);
                const float p1 = fmaf(step_sh[lr0 + 1], v1, xt * wih_sh[lr0 + 1]);
                const float p2 = fmaf(step_sh[lr0 + 2], v2, xt * wih_sh[lr0 + 2]);
                const float p3 = fmaf(step_sh[lr0 + 3], v3, xt * wih_sh[lr0 + 3]);
                __stcg((float4*)&g_pre[par][g * H + r0],
                       make_float4(p0, p1, p2, p3));
                warp_sq += p0 * p0 + p1 * p1 + p2 * p2 + p3 * p3;
            }
        }
        if (lane == 0) red_sh[warp] = warp_sq;
        __syncthreads();
        if (tid == 0) {
            float s = 0.0f;
            #pragma unroll
            for (int w = 0; w < NWARPS; ++w) s += red_sh[w];
            __stcg(&g_psq[par][cta], s);
        }

        // ============ per-GROUP barrier (16 CTAs) ============
        __threadfence();
        if (tid == 0) {
            const unsigned int snap = *epop;
            const unsigned int old = atomicAdd(cntp, 1u);
            if (old == CTAS_PER_GROUP - 1u) {
                *cntp = 0u;
                __threadfence();
                atomicAdd((unsigned int*)epop, 1u);
            } else {
                while (*epop == snap) { }
            }
        }
        __syncthreads();
        __threadfence();

        // ============ Phase B: norm + state update + h8 repack ==============
        if (tid == 0) {
            float s = 0.0f;
            #pragma unroll
            for (int c = 0; c < CTAS_PER_GROUP; ++c)
                s += __ldcg(&g_psq[par][g * CTAS_PER_GROUP + c]);
            coef_sh = lr * RADIUS_F * rsqrtf(s);
        }
        __syncthreads();
        const float cb = coef_sh;
        const float4* preg = (const float4*)&g_pre[par][g * H];
        float4* hmut = (float4*)h_sh;
        float m = 0.0f;
        {
            const int idx = tid;                 // 512 threads x float4 = H
            float4 p  = __ldcg(&preg[idx]);
            float4 hv = hmut[idx];
            hv.x = leak * hv.x + cb * p.x;
            hv.y = leak * hv.y + cb * p.y;
            hv.z = leak * hv.z + cb * p.z;
            hv.w = leak * hv.w + cb * p.w;
            hmut[idx] = hv;
            m = fmaxf(fmaxf(fabsf(hv.x), fabsf(hv.y)),
                      fmaxf(fabsf(hv.z), fabsf(hv.w)));
        }
        #pragma unroll
        for (int s = 16; s > 0; s >>= 1)
            m = fmaxf(m, __shfl_xor_sync(0xffffffffu, m, s));
        if (lane == 0) red_sh[warp] = m;
        __syncthreads();
        if (tid == 0) {
            float mm = 0.0f;
            #pragma unroll
            for (int w = 0; w < NWARPS; ++w) mm = fmaxf(mm, red_sh[w]);
            const float hstep = mm * (1.0f / 127.0f);
            hstep256_sh = hstep * (1.0f / 256.0f);
            invh_sh = (mm > 0.0f) ? 127.0f / mm : 0.0f;
        }
        __syncthreads();
        if (tid < NGRP) {
            const float inv = invh_sh;
            float4 ha = hs4[tid];
            float4 hb = hs4[tid + 256];
            int q0 = __float2int_rn(ha.x * inv);
            int q1 = __float2int_rn(ha.y * inv);
            int q2 = __float2int_rn(ha.z * inv);
            int q3 = __float2int_rn(ha.w * inv);
            int q4 = __float2int_rn(hb.x * inv);
            int q5 = __float2int_rn(hb.y * inv);
            int q6 = __float2int_rn(hb.z * inv);
            int q7 = __float2int_rn(hb.w * inv);
            hs8_sh[tid] = make_uint2(pack4(q0, q2, q4, q6),
                                     pack4(q1, q3, q5, q7));
        }
        if (tid < ROWS_PER_CTA) {
            __stcs(&out[(size_t)t * (G * H) + (size_t)g * H + rowbase + tid],
                   h_sh[rowbase + tid]);
        }
        __syncthreads();
    }
}

extern "C" void kernel_launch(void* const* d_in, const int* in_sizes, int n_in,
                              void* d_out, int out_size)
{
    const float* x    = (const float*)d_in[0];   // [T, 1]
    const float* W_ih = (const float*)d_in[1];   // [H, 1]
    const float* W_hh = (const float*)d_in[2];   // [G, H, H]
    float* out = (float*)d_out;                  // [T, G*H]

    rowscale_kernel<<<NROWS_TOTAL / 8, 256>>>(W_hh);
    quantize_kernel<<<(NROWS_TOTAL * NGRP + 255) / 256, 256>>>(W_hh);
    esn_persistent_kernel<<<NCTA, THREADS>>>(x, W_ih, out);
}

// round 8
// speedup vs baseline: 2.3197x; 1.0319x over previous
#include <cuda_runtime.h>
#include <cstddef>

// GroupedESNCell, round 7: numerics identical to R5/R6 (int16+int4, 4.02e-5).
// Throughput rework based on issue-bound diagnosis:
//   - packed f32x2 math kept in 64-bit registers end-to-end ("l" constraints)
//     -> eliminates per-op mov.b64 pack/unpack overhead
//   - explicit 2-stage register prefetch of weights in the k-loop
//   - per-group barrier + partial L1 residency kept from R6

#define G 8
#define H 2048
#define T_STEPS 4096
#define NCTA 128
#define CTAS_PER_GROUP (NCTA / G)             // 16
#define ROWS_PER_CTA (H / CTAS_PER_GROUP)     // 128
#define THREADS 512
#define NWARPS (THREADS / 32)                 // 16
#define ROWS_PER_WARP (ROWS_PER_CTA / NWARPS) // 8
#define RADIUS_F 100.0f
#define LEAKY_F 1.0f
#define NROWS_TOTAL (G * H)                   // 16384
#define NGRP 256                              // column groups per row (8 cols each)
#define L1_WARPS 4

typedef unsigned long long u64;
// bits of (-(2^23+32768), -(2^23+32768)) as packed f32x2
#define NEGM2 0xCB008000CB008000ULL

// ---- global scratch (allocation-free) ----
__device__ unsigned int g_wq[(size_t)G * H * H / 2];   // 67 MB q16 (split layout)
__device__ unsigned int g_wr[(size_t)G * H * H / 8];   // 16.8 MB q4 residual
__device__ float g_step[NROWS_TOTAL];
__device__ float g_pre[2][G * H];
__device__ float g_psq[2][NCTA];
__device__ unsigned int g_cnt[G * 32];
__device__ unsigned int g_epoch[G * 32];

// ============================================================================
// Prep kernel A: per-row max|w| -> step = rowmax/32767 (one warp per row)
// ============================================================================
__global__ void rowscale_kernel(const float* __restrict__ W_hh)
{
    const int warp = threadIdx.x >> 5;
    const int lane = threadIdx.x & 31;
    const int row  = blockIdx.x * 8 + warp;
    const float* w = W_hh + (size_t)row * H;

    float m = 0.0f;
    #pragma unroll
    for (int k = 0; k < H / 32; ++k)
        m = fmaxf(m, fabsf(w[lane + 32 * k]));
    #pragma unroll
    for (int s = 16; s > 0; s >>= 1)
        m = fmaxf(m, __shfl_xor_sync(0xffffffffu, m, s));
    if (lane == 0)
        g_step[row] = fmaxf(m, 1e-30f) * (1.0f / 32767.0f);
}

// ============================================================================
// Prep kernel B: quantize. One thread per (row, group): 8 elements
// (cols {4i..4i+3, 4i+1024..4i+1027}) -> uint4 biased-u16 + u32 of 8 nibbles
// ============================================================================
__global__ void quantize_kernel(const float* __restrict__ W_hh)
{
    const int gid = blockIdx.x * blockDim.x + threadIdx.x;
    if (gid >= NROWS_TOTAL * NGRP) return;
    const int row = gid >> 8;
    const int i   = gid & (NGRP - 1);
    const float* wr = W_hh + (size_t)row * H;
    const float inv = 1.0f / g_step[row];

    float4 wa = *(const float4*)(wr + 4 * i);
    float4 wb = *(const float4*)(wr + 4 * i + 1024);
    float v[8] = {wa.x, wa.y, wa.z, wa.w, wb.x, wb.y, wb.z, wb.w};

    unsigned int u16v[8];
    unsigned int nib = 0;
    #pragma unroll
    for (int j = 0; j < 8; ++j) {
        float s = v[j] * inv;
        int q = __float2int_rn(s);
        q = min(max(q, -32767), 32767);
        float r = s - (float)q;
        int q4 = __float2int_rn(r * 16.0f);
        q4 = min(max(q4, -8), 7);
        u16v[j] = (unsigned int)(q + 32768);
        nib |= (unsigned int)(q4 & 0xF) << (4 * j);
    }
    uint4 qs;
    qs.x = u16v[0] | (u16v[1] << 16);
    qs.y = u16v[2] | (u16v[3] << 16);
    qs.z = u16v[4] | (u16v[5] << 16);
    qs.w = u16v[6] | (u16v[7] << 16);
    ((uint4*)g_wq)[(size_t)row * NGRP + i] = qs;
    g_wr[(size_t)row * NGRP + i] = nib;
}

// ============================================================================
// packed f32x2 helpers, 64-bit registers end-to-end
// ============================================================================
// dequant packed pair of biased u16 -> f32x2 pair of centered q16 values
__device__ __forceinline__ u64 dq2(unsigned int p, u64 negm)
{
    u64 r;
    asm("{\n\t.reg .b32 lo, hi;\n\t"
        "prmt.b32 lo, %1, %2, 0x7610;\n\t"
        "prmt.b32 hi, %1, %2, 0x7632;\n\t"
        "mov.b64 %0, {lo, hi};\n\t"
        "add.rn.f32x2 %0, %0, %3;\n\t}"
        : "=l"(r) : "r"(p), "r"(0x4B000000u), "l"(negm));
    return r;
}
__device__ __forceinline__ u64 fma2(u64 a, u64 b, u64 c)
{
    u64 d;
    asm("fma.rn.f32x2 %0, %1, %2, %3;" : "=l"(d) : "l"(a), "l"(b), "l"(c));
    return d;
}
__device__ __forceinline__ float unpack_sum(u64 a)
{
    float lo, hi;
    asm("mov.b64 {%0, %1}, %2;" : "=f"(lo), "=f"(hi) : "l"(a));
    return lo + hi;
}
__device__ __forceinline__ unsigned int pack4(int a, int b, int c, int d)
{
    return (a & 0xFF) | ((b & 0xFF) << 8) | ((c & 0xFF) << 16) | ((d & 0xFF) << 24);
}
__device__ __forceinline__ void acc_res(int& dp, unsigned int x, uint2 hp)
{
    int e = (int)((x << 4) & 0xF0F0F0F0u);   // even cols: 16*q4 as s8
    int o = (int)(x & 0xF0F0F0F0u);
    dp = __dp4a(e, (int)hp.x, dp);
    dp = __dp4a(o, (int)hp.y, dp);
}

// 4-row block with explicit 2-stage register prefetch.
template <bool USE_L1>
__device__ __forceinline__ void do_block4(
    const uint4* __restrict__ wqb, const unsigned int* __restrict__ wrb,
    const ulonglong2* __restrict__ hs2, const uint2* __restrict__ hs8,
    int lane, float hstep256,
    float& v0, float& v1, float& v2, float& v3)
{
    const u64 negm = NEGM2;
    u64 a0 = 0ULL, a1 = 0ULL, a2 = 0ULL, a3 = 0ULL;   // (0.0f,0.0f)
    int dp0 = 0, dp1 = 0, dp2 = 0, dp3 = 0;

    uint4 qa[2], qb[2], qc[2], qd[2];
    unsigned int xa[2], xb[2], xc[2], xd[2];

#define LDW(slot, idx)                                              \
    do {                                                            \
        if (USE_L1) {                                               \
            qa[slot] = __ldca(&wqb[(idx)]);                         \
            qb[slot] = __ldca(&wqb[(idx) + NGRP]);                  \
            qc[slot] = __ldca(&wqb[(idx) + 2 * NGRP]);              \
            qd[slot] = __ldca(&wqb[(idx) + 3 * NGRP]);              \
            xa[slot] = __ldca(&wrb[(idx)]);                         \
            xb[slot] = __ldca(&wrb[(idx) + NGRP]);                  \
            xc[slot] = __ldca(&wrb[(idx) + 2 * NGRP]);              \
            xd[slot] = __ldca(&wrb[(idx) + 3 * NGRP]);              \
        } else {                                                    \
            qa[slot] = __ldcg(&wqb[(idx)]);                         \
            qb[slot] = __ldcg(&wqb[(idx) + NGRP]);                  \
            qc[slot] = __ldcg(&wqb[(idx) + 2 * NGRP]);              \
            qd[slot] = __ldcg(&wqb[(idx) + 3 * NGRP]);              \
            xa[slot] = __ldcg(&wrb[(idx)]);                         \
            xb[slot] = __ldcg(&wrb[(idx) + NGRP]);                  \
            xc[slot] = __ldcg(&wrb[(idx) + 2 * NGRP]);              \
            xd[slot] = __ldcg(&wrb[(idx) + 3 * NGRP]);              \
        }                                                           \
    } while (0)

    LDW(0, lane);                                   // prime k=0
    #pragma unroll
    for (int k = 0; k < 8; ++k) {
        const int cur = k & 1;
        if (k < 7) LDW(cur ^ 1, lane + 32 * (k + 1));   // prefetch k+1

        const int i = lane + 32 * k;
        ulonglong2 ha = hs2[i];          // cols 4i..4i+3 as 2 f32x2 pairs
        ulonglong2 hb = hs2[i + 256];    // cols 4i+1024..4i+1027
        uint2 hp = hs8[i];

        a0 = fma2(dq2(qa[cur].x, negm), ha.x, a0);
        a0 = fma2(dq2(qa[cur].y, negm), ha.y, a0);
        a0 = fma2(dq2(qa[cur].z, negm), hb.x, a0);
        a0 = fma2(dq2(qa[cur].w, negm), hb.y, a0);
        a1 = fma2(dq2(qb[cur].x, negm), ha.x, a1);
        a1 = fma2(dq2(qb[cur].y, negm), ha.y, a1);
        a1 = fma2(dq2(qb[cur].z, negm), hb.x, a1);
        a1 = fma2(dq2(qb[cur].w, negm), hb.y, a1);
        a2 = fma2(dq2(qc[cur].x, negm), ha.x, a2);
        a2 = fma2(dq2(qc[cur].y, negm), ha.y, a2);
        a2 = fma2(dq2(qc[cur].z, negm), hb.x, a2);
        a2 = fma2(dq2(qc[cur].w, negm), hb.y, a2);
        a3 = fma2(dq2(qd[cur].x, negm), ha.x, a3);
        a3 = fma2(dq2(qd[cur].y, negm), ha.y, a3);
        a3 = fma2(dq2(qd[cur].z, negm), hb.x, a3);
        a3 = fma2(dq2(qd[cur].w, negm), hb.y, a3);

        acc_res(dp0, xa[cur], hp);
        acc_res(dp1, xb[cur], hp);
        acc_res(dp2, xc[cur], hp);
        acc_res(dp3, xd[cur], hp);
    }
#undef LDW

    v0 = fmaf(hstep256, (float)dp0, unpack_sum(a0));
    v1 = fmaf(hstep256, (float)dp1, unpack_sum(a1));
    v2 = fmaf(hstep256, (float)dp2, unpack_sum(a2));
    v3 = fmaf(hstep256, (float)dp3, unpack_sum(a3));
}

// ============================================================================
// Persistent recurrence kernel
// ============================================================================
__global__ __launch_bounds__(THREADS, 1)
void esn_persistent_kernel(const float* __restrict__ x,
                           const float* __restrict__ W_ih,
                           float* __restrict__ out)
{
    __shared__ __align__(16) float h_sh[H];
    __shared__ __align__(8) uint2 hs8_sh[NGRP];
    __shared__ float x_sh[T_STEPS];
    __shared__ float wih_sh[ROWS_PER_CTA];
    __shared__ float step_sh[ROWS_PER_CTA];
    __shared__ float red_sh[NWARPS];
    __shared__ float coef_sh;
    __shared__ float hstep256_sh;
    __shared__ float invh_sh;

    const int tid  = threadIdx.x;
    const int cta  = blockIdx.x;
    const int g    = cta / CTAS_PER_GROUP;
    const int sub  = cta % CTAS_PER_GROUP;
    const int rowbase = sub * ROWS_PER_CTA;
    const int warp = tid >> 5;
    const int lane = tid & 31;

    const float lr   = (LEAKY_F * (float)(G - g)) / (float)G;
    const float leak = 1.0f - lr;

    const uint4* Wq = (const uint4*)g_wq + (size_t)g * H * NGRP;
    const unsigned int* Wr = g_wr + (size_t)g * H * NGRP;
    const ulonglong2* hs2 = (const ulonglong2*)h_sh;
    const float4* hs4 = (const float4*)h_sh;

    for (int i = tid; i < H; i += THREADS) h_sh[i] = 0.0f;
    for (int i = tid; i < NGRP; i += THREADS) hs8_sh[i] = make_uint2(0u, 0u);
    for (int i = tid; i < T_STEPS; i += THREADS) x_sh[i] = x[i];
    if (tid < ROWS_PER_CTA) {
        wih_sh[tid]  = W_ih[rowbase + tid];
        step_sh[tid] = g_step[g * H + rowbase + tid];
    }
    if (tid == 0) { hstep256_sh = 0.0f; invh_sh = 0.0f; }
    __syncthreads();

    unsigned int* const cntp = &g_cnt[g * 32];
    volatile unsigned int* const epop = (volatile unsigned int*)&g_epoch[g * 32];

    for (int t = 0; t < T_STEPS; ++t) {
        const int par = t & 1;
        const float xt = x_sh[t];
        const float hstep256 = hstep256_sh;

        // ============ Phase A: quantized matvec, 8 rows per warp ============
        float warp_sq = 0.0f;
        const int wrow0 = rowbase + warp * ROWS_PER_WARP;

        #pragma unroll 1
        for (int rr = 0; rr < ROWS_PER_WARP; rr += 4) {
            const int r0 = wrow0 + rr;
            const uint4* wqb = Wq + (size_t)r0 * NGRP;
            const unsigned int* wrb = Wr + (size_t)r0 * NGRP;

            float v0, v1, v2, v3;
            if (warp < L1_WARPS)
                do_block4<true >(wqb, wrb, hs2, hs8_sh, lane, hstep256,
                                 v0, v1, v2, v3);
            else
                do_block4<false>(wqb, wrb, hs2, hs8_sh, lane, hstep256,
                                 v0, v1, v2, v3);

            #pragma unroll
            for (int s = 16; s > 0; s >>= 1) {
                v0 += __shfl_xor_sync(0xffffffffu, v0, s);
                v1 += __shfl_xor_sync(0xffffffffu, v1, s);
                v2 += __shfl_xor_sync(0xffffffffu, v2, s);
                v3 += __shfl_xor_sync(0xffffffffu, v3, s);
            }
            if (lane == 0) {
                const int lr0 = r0 - rowbase;
                const float p0 = fmaf(step_sh[lr0],     v0, xt * wih_sh[lr0]);
                const float p1 = fmaf(step_sh[lr0 + 1], v1, xt * wih_sh[lr0 + 1]);
                const float p2 = fmaf(step_sh[lr0 + 2], v2, xt * wih_sh[lr0 + 2]);
                const float p3 = fmaf(step_sh[lr0 + 3], v3, xt * wih_sh[lr0 + 3]);
                __stcg((float4*)&g_pre[par][g * H + r0],
                       make_float4(p0, p1, p2, p3));
                warp_sq += p0 * p0 + p1 * p1 + p2 * p2 + p3 * p3;
            }
        }
        if (lane == 0) red_sh[warp] = warp_sq;
        __syncthreads();
        if (tid == 0) {
            float s = 0.0f;
            #pragma unroll
            for (int w = 0; w < NWARPS; ++w) s += red_sh[w];
            __stcg(&g_psq[par][cta], s);
        }

        // ============ per-GROUP barrier (16 CTAs) ============
        __threadfence();
        if (tid == 0) {
            const unsigned int snap = *epop;
            const unsigned int old = atomicAdd(cntp, 1u);
            if (old == CTAS_PER_GROUP - 1u) {
                *cntp = 0u;
                __threadfence();
                atomicAdd((unsigned int*)epop, 1u);
            } else {
                while (*epop == snap) { }
            }
        }
        __syncthreads();
        __threadfence();

        // ============ Phase B: norm + state update + h8 repack ==============
        if (tid == 0) {
            float s = 0.0f;
            #pragma unroll
            for (int c = 0; c < CTAS_PER_GROUP; ++c)
                s += __ldcg(&g_psq[par][g * CTAS_PER_GROUP + c]);
            coef_sh = lr * RADIUS_F * rsqrtf(s);
        }
        __syncthreads();
        const float cb = coef_sh;
        const float4* preg = (const float4*)&g_pre[par][g * H];
        float4* hmut = (float4*)h_sh;
        float m = 0.0f;
        {
            const int idx = tid;                 // 512 threads x float4 = H
            float4 p  = __ldcg(&preg[idx]);
            float4 hv = hmut[idx];
            hv.x = leak * hv.x + cb * p.x;
            hv.y = leak * hv.y + cb * p.y;
            hv.z = leak * hv.z + cb * p.z;
            hv.w = leak * hv.w + cb * p.w;
            hmut[idx] = hv;
            m = fmaxf(fmaxf(fabsf(hv.x), fabsf(hv.y)),
                      fmaxf(fabsf(hv.z), fabsf(hv.w)));
        }
        #pragma unroll
        for (int s = 16; s > 0; s >>= 1)
            m = fmaxf(m, __shfl_xor_sync(0xffffffffu, m, s));
        if (lane == 0) red_sh[warp] = m;
        __syncthreads();
        if (tid == 0) {
            float mm = 0.0f;
            #pragma unroll
            for (int w = 0; w < NWARPS; ++w) mm = fmaxf(mm, red_sh[w]);
            const float hstep = mm * (1.0f / 127.0f);
            hstep256_sh = hstep * (1.0f / 256.0f);
            invh_sh = (mm > 0.0f) ? 127.0f / mm : 0.0f;
        }
        __syncthreads();
        if (tid < NGRP) {
            const float inv = invh_sh;
            float4 ha = hs4[tid];
            float4 hb = hs4[tid + 256];
            int q0 = __float2int_rn(ha.x * inv);
            int q1 = __float2int_rn(ha.y * inv);
            int q2 = __float2int_rn(ha.z * inv);
            int q3 = __float2int_rn(ha.w * inv);
            int q4 = __float2int_rn(hb.x * inv);
            int q5 = __float2int_rn(hb.y * inv);
            int q6 = __float2int_rn(hb.z * inv);
            int q7 = __float2int_rn(hb.w * inv);
            hs8_sh[tid] = make_uint2(pack4(q0, q2, q4, q6),
                                     pack4(q1, q3, q5, q7));
        }
        if (tid < ROWS_PER_CTA) {
            __stcs(&out[(size_t)t * (G * H) + (size_t)g * H + rowbase + tid],
                   h_sh[rowbase + tid]);
        }
        __syncthreads();
    }
}

extern "C" void kernel_launch(void* const* d_in, const int* in_sizes, int n_in,
                              void* d_out, int out_size)
{
    const float* x    = (const float*)d_in[0];   // [T, 1]
    const float* W_ih = (const float*)d_in[1];   // [H, 1]
    const float* W_hh = (const float*)d_in[2];   // [G, H, H]
    float* out = (float*)d_out;                  // [T, G*H]

    rowscale_kernel<<<NROWS_TOTAL / 8, 256>>>(W_hh);
    quantize_kernel<<<(NROWS_TOTAL * NGRP + 255) / 256, 256>>>(W_hh);
    esn_persistent_kernel<<<NCTA, THREADS>>>(x, W_ih, out);
}

// round 9
// speedup vs baseline: 2.3357x; 1.0069x over previous
#include <cuda_runtime.h>
#include <cstddef>

// GroupedESNCell, round 7: numerics identical to R5/R6 (int16+int4, 4.02e-5).
// Throughput rework based on issue-bound diagnosis:
//   - packed f32x2 math kept in 64-bit registers end-to-end ("l" constraints)
//     -> eliminates per-op mov.b64 pack/unpack overhead
//   - explicit 2-stage register prefetch of weights in the k-loop
//   - per-group barrier + partial L1 residency kept from R6

#define G 8
#define H 2048
#define T_STEPS 4096
#define NCTA 128
#define CTAS_PER_GROUP (NCTA / G)             // 16
#define ROWS_PER_CTA (H / CTAS_PER_GROUP)     // 128
#define THREADS 512
#define NWARPS (THREADS / 32)                 // 16
#define ROWS_PER_WARP (ROWS_PER_CTA / NWARPS) // 8
#define RADIUS_F 100.0f
#define LEAKY_F 1.0f
#define NROWS_TOTAL (G * H)                   // 16384
#define NGRP 256                              // column groups per row (8 cols each)
#define L1_WARPS 4

typedef unsigned long long u64;
// bits of (-(2^23+32768), -(2^23+32768)) as packed f32x2
#define NEGM2 0xCB008000CB008000ULL

// ---- global scratch (allocation-free) ----
__device__ unsigned int g_wq[(size_t)G * H * H / 2];   // 67 MB q16 (split layout)
__device__ unsigned int g_wr[(size_t)G * H * H / 8];   // 16.8 MB q4 residual
__device__ float g_step[NROWS_TOTAL];
__device__ float g_pre[2][G * H];
__device__ float g_psq[2][NCTA];
__device__ unsigned int g_cnt[G * 32];
__device__ unsigned int g_epoch[G * 32];

// ============================================================================
// Prep kernel A: per-row max|w| -> step = rowmax/32767 (one warp per row)
// ============================================================================
__global__ void rowscale_kernel(const float* __restrict__ W_hh)
{
    const int warp = threadIdx.x >> 5;
    const int lane = threadIdx.x & 31;
    const int row  = blockIdx.x * 8 + warp;
    const float* w = W_hh + (size_t)row * H;

    float m = 0.0f;
    #pragma unroll
    for (int k = 0; k < H / 32; ++k)
        m = fmaxf(m, fabsf(w[lane + 32 * k]));
    #pragma unroll
    for (int s = 16; s > 0; s >>= 1)
        m = fmaxf(m, __shfl_xor_sync(0xffffffffu, m, s));
    if (lane == 0)
        g_step[row] = fmaxf(m, 1e-30f) * (1.0f / 32767.0f);
}

// ============================================================================
// Prep kernel B: quantize. One thread per (row, group): 8 elements
// (cols {4i..4i+3, 4i+1024..4i+1027}) -> uint4 biased-u16 + u32 of 8 nibbles
// ============================================================================
__global__ void quantize_kernel(const float* __restrict__ W_hh)
{
    const int gid = blockIdx.x * blockDim.x + threadIdx.x;
    if (gid >= NROWS_TOTAL * NGRP) return;
    const int row = gid >> 8;
    const int i   = gid & (NGRP - 1);
    const float* wr = W_hh + (size_t)row * H;
    const float inv = 1.0f / g_step[row];

    float4 wa = *(const float4*)(wr + 4 * i);
    float4 wb = *(const float4*)(wr + 4 * i + 1024);
    float v[8] = {wa.x, wa.y, wa.z, wa.w, wb.x, wb.y, wb.z, wb.w};

    unsigned int u16v[8];
    unsigned int nib = 0;
    #pragma unroll
    for (int j = 0; j < 8; ++j) {
        float s = v[j] * inv;
        int q = __float2int_rn(s);
        q = min(max(q, -32767), 32767);
        float r = s - (float)q;
        int q4 = __float2int_rn(r * 16.0f);
        q4 = min(max(q4, -8), 7);
        u16v[j] = (unsigned int)(q + 32768);
        nib |= (unsigned int)(q4 & 0xF) << (4 * j);
    }
    uint4 qs;
    qs.x = u16v[0] | (u16v[1] << 16);
    qs.y = u16v[2] | (u16v[3] << 16);
    qs.z = u16v[4] | (u16v[5] << 16);
    qs.w = u16v[6] | (u16v[7] << 16);
    ((uint4*)g_wq)[(size_t)row * NGRP + i] = qs;
    g_wr[(size_t)row * NGRP + i] = nib;
}

// ============================================================================
// packed f32x2 helpers, 64-bit registers end-to-end
// ============================================================================
// dequant packed pair of biased u16 -> f32x2 pair of centered q16 values
__device__ __forceinline__ u64 dq2(unsigned int p, u64 negm)
{
    u64 r;
    asm("{\n\t.reg .b32 lo, hi;\n\t"
        "prmt.b32 lo, %1, %2, 0x7610;\n\t"
        "prmt.b32 hi, %1, %2, 0x7632;\n\t"
        "mov.b64 %0, {lo, hi};\n\t"
        "add.rn.f32x2 %0, %0, %3;\n\t}"
        : "=l"(r) : "r"(p), "r"(0x4B000000u), "l"(negm));
    return r;
}
__device__ __forceinline__ u64 fma2(u64 a, u64 b, u64 c)
{
    u64 d;
    asm("fma.rn.f32x2 %0, %1, %2, %3;" : "=l"(d) : "l"(a), "l"(b), "l"(c));
    return d;
}
__device__ __forceinline__ float unpack_sum(u64 a)
{
    float lo, hi;
    asm("mov.b64 {%0, %1}, %2;" : "=f"(lo), "=f"(hi) : "l"(a));
    return lo + hi;
}
__device__ __forceinline__ unsigned int pack4(int a, int b, int c, int d)
{
    return (a & 0xFF) | ((b & 0xFF) << 8) | ((c & 0xFF) << 16) | ((d & 0xFF) << 24);
}
__device__ __forceinline__ void acc_res(int& dp, unsigned int x, uint2 hp)
{
    int e = (int)((x << 4) & 0xF0F0F0F0u);   // even cols: 16*q4 as s8
    int o = (int)(x & 0xF0F0F0F0u);
    dp = __dp4a(e, (int)hp.x, dp);
    dp = __dp4a(o, (int)hp.y, dp);
}

// 4-row block with explicit 2-stage register prefetch.
template <bool USE_L1>
__device__ __forceinline__ void do_block4(
    const uint4* __restrict__ wqb, const unsigned int* __restrict__ wrb,
    const ulonglong2* __restrict__ hs2, const uint2* __restrict__ hs8,
    int lane, float hstep256,
    float& v0, float& v1, float& v2, float& v3)
{
    const u64 negm = NEGM2;
    u64 a0 = 0ULL, a1 = 0ULL, a2 = 0ULL, a3 = 0ULL;   // (0.0f,0.0f)
    int dp0 = 0, dp1 = 0, dp2 = 0, dp3 = 0;

    uint4 qa[2], qb[2], qc[2], qd[2];
    unsigned int xa[2], xb[2], xc[2], xd[2];

#define LDW(slot, idx)                                              \
    do {                                                            \
        if (USE_L1) {                                               \
            qa[slot] = __ldca(&wqb[(idx)]);                         \
            qb[slot] = __ldca(&wqb[(idx) + NGRP]);                  \
            qc[slot] = __ldca(&wqb[(idx) + 2 * NGRP]);              \
            qd[slot] = __ldca(&wqb[(idx) + 3 * NGRP]);              \
            xa[slot] = __ldca(&wrb[(idx)]);                         \
            xb[slot] = __ldca(&wrb[(idx) + NGRP]);                  \
            xc[slot] = __ldca(&wrb[(idx) + 2 * NGRP]);              \
            xd[slot] = __ldca(&wrb[(idx) + 3 * NGRP]);              \
        } else {                                                    \
            qa[slot] = __ldcg(&wqb[(idx)]);                         \
            qb[slot] = __ldcg(&wqb[(idx) + NGRP]);                  \
            qc[slot] = __ldcg(&wqb[(idx) + 2 * NGRP]);              \
            qd[slot] = __ldcg(&wqb[(idx) + 3 * NGRP]);              \
            xa[slot] = __ldcg(&wrb[(idx)]);                         \
            xb[slot] = __ldcg(&wrb[(idx) + NGRP]);                  \
            xc[slot] = __ldcg(&wrb[(idx) + 2 * NGRP]);              \
            xd[slot] = __ldcg(&wrb[(idx) + 3 * NGRP]);              \
        }                                                           \
    } while (0)

    LDW(0, lane);                                   // prime k=0
    #pragma unroll
    for (int k = 0; k < 8; ++k) {
        const int cur = k & 1;
        if (k < 7) LDW(cur ^ 1, lane + 32 * (k + 1));   // prefetch k+1

        const int i = lane + 32 * k;
        ulonglong2 ha = hs2[i];          // cols 4i..4i+3 as 2 f32x2 pairs
        ulonglong2 hb = hs2[i + 256];    // cols 4i+1024..4i+1027
        uint2 hp = hs8[i];

        a0 = fma2(dq2(qa[cur].x, negm), ha.x, a0);
        a0 = fma2(dq2(qa[cur].y, negm), ha.y, a0);
        a0 = fma2(dq2(qa[cur].z, negm), hb.x, a0);
        a0 = fma2(dq2(qa[cur].w, negm), hb.y, a0);
        a1 = fma2(dq2(qb[cur].x, negm), ha.x, a1);
        a1 = fma2(dq2(qb[cur].y, negm), ha.y, a1);
        a1 = fma2(dq2(qb[cur].z, negm), hb.x, a1);
        a1 = fma2(dq2(qb[cur].w, negm), hb.y, a1);
        a2 = fma2(dq2(qc[cur].x, negm), ha.x, a2);
        a2 = fma2(dq2(qc[cur].y, negm), ha.y, a2);
        a2 = fma2(dq2(qc[cur].z, negm), hb.x, a2);
        a2 = fma2(dq2(qc[cur].w, negm), hb.y, a2);
        a3 = fma2(dq2(qd[cur].x, negm), ha.x, a3);
        a3 = fma2(dq2(qd[cur].y, negm), ha.y, a3);
        a3 = fma2(dq2(qd[cur].z, negm), hb.x, a3);
        a3 = fma2(dq2(qd[cur].w, negm), hb.y, a3);

        acc_res(dp0, xa[cur], hp);
        acc_res(dp1, xb[cur], hp);
        acc_res(dp2, xc[cur], hp);
        acc_res(dp3, xd[cur], hp);
    }
#undef LDW

    v0 = fmaf(hstep256, (float)dp0, unpack_sum(a0));
    v1 = fmaf(hstep256, (float)dp1, unpack_sum(a1));
    v2 = fmaf(hstep256, (float)dp2, unpack_sum(a2));
    v3 = fmaf(hstep256, (float)dp3, unpack_sum(a3));
}

// ============================================================================
// Persistent recurrence kernel
// ============================================================================
__global__ __launch_bounds__(THREADS, 1)
void esn_persistent_kernel(const float* __restrict__ x,
                           const float* __restrict__ W_ih,
                           float* __restrict__ out)
{
    __shared__ __align__(16) float h_sh[H];
    __shared__ __align__(8) uint2 hs8_sh[NGRP];
    __shared__ float x_sh[T_STEPS];
    __shared__ float wih_sh[ROWS_PER_CTA];
    __shared__ float step_sh[ROWS_PER_CTA];
    __shared__ float red_sh[NWARPS];
    __shared__ float coef_sh;
    __shared__ float hstep256_sh;
    __shared__ float invh_sh;

    const int tid  = threadIdx.x;
    const int cta  = blockIdx.x;
    const int g    = cta / CTAS_PER_GROUP;
    const int sub  = cta % CTAS_PER_GROUP;
    const int rowbase = sub * ROWS_PER_CTA;
    const int warp = tid >> 5;
    const int lane = tid & 31;

    const float lr   = (LEAKY_F * (float)(G - g)) / (float)G;
    const float leak = 1.0f - lr;

    const uint4* Wq = (const uint4*)g_wq + (size_t)g * H * NGRP;
    const unsigned int* Wr = g_wr + (size_t)g * H * NGRP;
    const ulonglong2* hs2 = (const ulonglong2*)h_sh;
    const float4* hs4 = (const float4*)h_sh;

    for (int i = tid; i < H; i += THREADS) h_sh[i] = 0.0f;
    for (int i = tid; i < NGRP; i += THREADS) hs8_sh[i] = make_uint2(0u, 0u);
    for (int i = tid; i < T_STEPS; i += THREADS) x_sh[i] = x[i];
    if (tid < ROWS_PER_CTA) {
        wih_sh[tid]  = W_ih[rowbase + tid];
        step_sh[tid] = g_step[g * H + rowbase + tid];
    }
    if (tid == 0) { hstep256_sh = 0.0f; invh_sh = 0.0f; }
    __syncthreads();

    unsigned int* const cntp = &g_cnt[g * 32];
    volatile unsigned int* const epop = (volatile unsigned int*)&g_epoch[g * 32];

    for (int t = 0; t < T_STEPS; ++t) {
        const int par = t & 1;
        const float xt = x_sh[t];
        const float hstep256 = hstep256_sh;

        // ============ Phase A: quantized matvec, 8 rows per warp ============
        float warp_sq = 0.0f;
        const int wrow0 = rowbase + warp * ROWS_PER_WARP;

        #pragma unroll 1
        for (int rr = 0; rr < ROWS_PER_WARP; rr += 4) {
            const int r0 = wrow0 + rr;
            const uint4* wqb = Wq + (size_t)r0 * NGRP;
            const unsigned int* wrb = Wr + (size_t)r0 * NGRP;

            float v0, v1, v2, v3;
            if (warp < L1_WARPS)
                do_block4<true >(wqb, wrb, hs2, hs8_sh, lane, hstep256,
                                 v0, v1, v2, v3);
            else
                do_block4<false>(wqb, wrb, hs2, hs8_sh, lane, hstep256,
                                 v0, v1, v2, v3);

            #pragma unroll
            for (int s = 16; s > 0; s >>= 1) {
                v0 += __shfl_xor_sync(0xffffffffu, v0, s);
                v1 += __shfl_xor_sync(0xffffffffu, v1, s);
                v2 += __shfl_xor_sync(0xffffffffu, v2, s);
                v3 += __shfl_xor_sync(0xffffffffu, v3, s);
            }
            if (lane == 0) {
                const int lr0 = r0 - rowbase;
                const float p0 = fmaf(step_sh[lr0],     v0, xt * wih_sh[lr0]);
                const float p1 = fmaf(step_sh[lr0 + 1], v1, xt * wih_sh[lr0 + 1]);
                const float p2 = fmaf(step_sh[lr0 + 2], v2, xt * wih_sh[lr0 + 2]);
                const float p3 = fmaf(step_sh[lr0 + 3], v3, xt * wih_sh[lr0 + 3]);
                __stcg((float4*)&g_pre[par][g * H + r0],
                       make_float4(p0, p1, p2, p3));
                warp_sq += p0 * p0 + p1 * p1 + p2 * p2 + p3 * p3;
            }
        }
        if (lane == 0) red_sh[warp] = warp_sq;
        __syncthreads();
        if (tid == 0) {
            float s = 0.0f;
            #pragma unroll
            for (int w = 0; w < NWARPS; ++w) s += red_sh[w];
            __stcg(&g_psq[par][cta], s);
        }

        // ============ per-GROUP barrier (16 CTAs) ============
        __threadfence();
        if (tid == 0) {
            const unsigned int snap = *epop;
            const unsigned int old = atomicAdd(cntp, 1u);
            if (old == CTAS_PER_GROUP - 1u) {
                *cntp = 0u;
                __threadfence();
                atomicAdd((unsigned int*)epop, 1u);
            } else {
                while (*epop == snap) { }
            }
        }
        __syncthreads();
        __threadfence();

        // ============ Phase B: norm + state update + h8 repack ==============
        if (tid == 0) {
            float s = 0.0f;
            #pragma unroll
            for (int c = 0; c < CTAS_PER_GROUP; ++c)
                s += __ldcg(&g_psq[par][g * CTAS_PER_GROUP + c]);
            coef_sh = lr * RADIUS_F * rsqrtf(s);
        }
        __syncthreads();
        const float cb = coef_sh;
        const float4* preg = (const float4*)&g_pre[par][g * H];
        float4* hmut = (float4*)h_sh;
        float m = 0.0f;
        {
            const int idx = tid;                 // 512 threads x float4 = H
            float4 p  = __ldcg(&preg[idx]);
            float4 hv = hmut[idx];
            hv.x = leak * hv.x + cb * p.x;
            hv.y = leak * hv.y + cb * p.y;
            hv.z = leak * hv.z + cb * p.z;
            hv.w = leak * hv.w + cb * p.w;
            hmut[idx] = hv;
            m = fmaxf(fmaxf(fabsf(hv.x), fabsf(hv.y)),
                      fmaxf(fabsf(hv.z), fabsf(hv.w)));
        }
        #pragma unroll
        for (int s = 16; s > 0; s >>= 1)
            m = fmaxf(m, __shfl_xor_sync(0xffffffffu, m, s));
        if (lane == 0) red_sh[warp] = m;
        __syncthreads();
        if (tid == 0) {
            float mm = 0.0f;
            #pragma unroll
            for (int w = 0; w < NWARPS; ++w) mm = fmaxf(mm, red_sh[w]);
            const float hstep = mm * (1.0f / 127.0f);
            hstep256_sh = hstep * (1.0f / 256.0f);
            invh_sh = (mm > 0.0f) ? 127.0f / mm : 0.0f;
        }
        __syncthreads();
        if (tid < NGRP) {
            const float inv = invh_sh;
            float4 ha = hs4[tid];
            float4 hb = hs4[tid + 256];
            int q0 = __float2int_rn(ha.x * inv);
            int q1 = __float2int_rn(ha.y * inv);
            int q2 = __float2int_rn(ha.z * inv);
            int q3 = __float2int_rn(ha.w * inv);
            int q4 = __float2int_rn(hb.x * inv);
            int q5 = __float2int_rn(hb.y * inv);
            int q6 = __float2int_rn(hb.z * inv);
            int q7 = __float2int_rn(hb.w * inv);
            hs8_sh[tid] = make_uint2(pack4(q0, q2, q4, q6),
                                     pack4(q1, q3, q5, q7));
        }
        if (tid < ROWS_PER_CTA) {
            __stcs(&out[(size_t)t * (G * H) + (size_t)g * H + rowbase + tid],
                   h_sh[rowbase + tid]);
        }
        __syncthreads();
    }
}

extern "C" void kernel_launch(void* const* d_in, const int* in_sizes, int n_in,
                              void* d_out, int out_size)
{
    const float* x    = (const float*)d_in[0];   // [T, 1]
    const float* W_ih = (const float*)d_in[1];   // [H, 1]
    const float* W_hh = (const float*)d_in[2];   // [G, H, H]
    float* out = (float*)d_out;                  // [T, G*H]

    rowscale_kernel<<<NROWS_TOTAL / 8, 256>>>(W_hh);
    quantize_kernel<<<(NROWS_TOTAL * NGRP + 255) / 256, 256>>>(W_hh);
    esn_persistent_kernel<<<NCTA, THREADS>>>(x, W_ih, out);
}